// round 7
// baseline (speedup 1.0000x reference)
#include <cuda_runtime.h>
#include <math.h>

#define BSZ 4

// ---------------- scratch (device globals; no allocations allowed) ----------
__device__ float g_v  [16777216];   // [4,64,256,256]
__device__ float g_x1d[ 4194304];   // [4,64,128,128]
__device__ float g_x2d[ 1572864];   // [4,96,64,64]
__device__ float g_xb [ 2097152];   // [4,128,64,64]
__device__ float g_x2c[14680064];   // [4,224,128,128] (x2 at coff 128)
__device__ float g_x2o[ 6291456];   // [4,96,128,128]
__device__ float g_x1c[41943040];   // [4,160,256,256] (x1 at coff 96)
__device__ float g_x1o[16777216];   // [4,64,256,256]

__device__ float g_XW [ 3932160];   // transposed: [H][BC*m2c]
__device__ float g_XF [  368640];   // [BC,2m1,m2] complex
__device__ float g_OF [  368640];   // [B,Co,2m1,m2] complex
__device__ float g_Z  [ 1572864];   // [B,Co,H,m2] complex (scaled)
__device__ float g_tw [   26112];   // twiddle tables (complex interleaved)

#define TW0 0
#define TH0 3072
#define TW1 9216
#define TH1 10240
#define TW2 12288
#define TH2 12544

__device__ __forceinline__ float gelu_f(float x) {
    return 0.5f * x * (1.0f + erff(x * 0.70710678118654752f));
}

// ---------------- twiddle init -----------------------------------------------
__global__ void k_init_tw() {
    const int cfg[3][5] = {{256,12,12,TW0,TH0},{128,8,8,TW1,TH1},{64,4,4,TW2,TH2}};
    int tid = blockIdx.x * blockDim.x + threadIdx.x;
    int nth = gridDim.x * blockDim.x;
    for (int c = 0; c < 3; c++) {
        int H = cfg[c][0], m1 = cfg[c][1], m2 = cfg[c][2];
        int offW = cfg[c][3], offH = cfg[c][4];
        int nW = H * m2;
        for (int e = tid; e < nW; e += nth) {
            int w = e / m2, kw = e % m2;
            int p = (w * kw) % H;
            double s, co; sincos(2.0 * 3.14159265358979323846 * (double)p / (double)H, &s, &co);
            g_tw[(offW + e) * 2]     = (float)co;
            g_tw[(offW + e) * 2 + 1] = (float)(-s);
        }
        int m1t2 = 2 * m1;
        int nH = H * m1t2;
        for (int e = tid; e < nH; e += nth) {
            int h = e / m1t2, j = e % m1t2;
            int kh = (j < m1) ? j : (H - 2 * m1 + j);
            int p = (kh * h) % H;
            double s, co; sincos(2.0 * 3.14159265358979323846 * (double)p / (double)H, &s, &co);
            g_tw[(offH + e) * 2]     = (float)co;
            g_tw[(offH + e) * 2 + 1] = (float)(-s);
        }
    }
}

// ---------------- lift: tiled 64px x 64c -------------------------------------
__global__ void k_lift(const float* __restrict__ x, const float* __restrict__ w,
                       const float* __restrict__ bb) {
    __shared__ float xs6[64][8];
    __shared__ float ws6[64][8];
    const int HW = 256 * 256;
    int b  = blockIdx.x >> 10;
    int p0 = (blockIdx.x & 1023) << 6;
    int tid = threadIdx.x;

    const float* xp = x + ((size_t)b * HW + p0) * 6;
    for (int l = tid; l < 384; l += 256) xs6[l / 6][l % 6] = xp[l];
    for (int l = tid; l < 384; l += 256) ws6[l / 6][l % 6] = w[l];
    __syncthreads();

    int ty = tid >> 4, tx = tid & 15;        // c group, px group
    #pragma unroll
    for (int cr = 0; cr < 4; cr++) {
        int c = ty * 4 + cr;
        float bias = bb[c];
        float res[4];
        #pragma unroll
        for (int pc = 0; pc < 4; pc++) {
            int p = tx * 4 + pc;
            float acc = bias;
            #pragma unroll
            for (int k = 0; k < 6; k++) acc += ws6[c][k] * xs6[p][k];
            res[pc] = acc;
        }
        *(float4*)(g_v + (size_t)(b * 64 + c) * HW + p0 + tx * 4) =
            make_float4(res[0], res[1], res[2], res[3]);
    }
}

// ------- fwd DFT along W: x rows -> XWt[h][bc*m2c] (transposed) -------------
__global__ void k_fwd_w(const float* __restrict__ xin, int H, int W, int m2,
                        const float* __restrict__ tw, int BC) {
    __shared__ float xs[64][68];
    __shared__ float tws[64][24];
    int m2c = 2 * m2;
    int r0 = blockIdx.x * 64;
    int tid = threadIdx.x;
    int row_l = tid & 31;
    int kc0 = tid >> 5;
    bool v1 = (kc0 + 8 < m2c), v2 = (kc0 + 16 < m2c);
    float a00 = 0.f, a01 = 0.f, a02 = 0.f, a10 = 0.f, a11 = 0.f, a12 = 0.f;

    for (int k0 = 0; k0 < W; k0 += 64) {
        for (int l = tid; l < 64 * 16; l += 256) {
            int r = l >> 4, k4 = (l & 15) * 4;
            float4 v = *(const float4*)(xin + (size_t)(r0 + r) * W + k0 + k4);
            *(float4*)&xs[r][k4] = v;
        }
        for (int l = tid; l < 64 * m2c; l += 256) {
            int k = l / m2c, kc = l % m2c;
            tws[k][kc] = tw[(size_t)(k0 + k) * m2c + kc];
        }
        __syncthreads();
        #pragma unroll 4
        for (int k = 0; k < 64; k++) {
            float x0 = xs[row_l][k];
            float x1 = xs[row_l + 32][k];
            float t0 = tws[k][kc0];
            a00 += x0 * t0; a10 += x1 * t0;
            if (v1) { float t1 = tws[k][kc0 + 8];  a01 += x0 * t1; a11 += x1 * t1; }
            if (v2) { float t2 = tws[k][kc0 + 16]; a02 += x0 * t2; a12 += x1 * t2; }
        }
        __syncthreads();
    }
    int r = r0 + row_l;
    int bc = r / H, h = r - bc * H;
    size_t base = ((size_t)h * BC + bc) * m2c;
    g_XW[base + kc0] = a00;
    if (v1) g_XW[base + kc0 + 8]  = a01;
    if (v2) g_XW[base + kc0 + 16] = a02;
    r = r0 + row_l + 32;
    bc = r / H; h = r - bc * H;
    base = ((size_t)h * BC + bc) * m2c;
    g_XW[base + kc0] = a10;
    if (v1) g_XW[base + kc0 + 8]  = a11;
    if (v2) g_XW[base + kc0 + 16] = a12;
}

// ------- fwd DFT along H as GEMM over transposed XW --------------------------
__global__ void k_fwd_h(int H, int BCm2, int m1, int m2, const float* __restrict__ tw) {
    __shared__ float xs[64][64];
    __shared__ float tws[64][48];
    int m1t2 = 2 * m1;
    int cc0 = blockIdx.x * 32;
    int tid = threadIdx.x;
    int cl = tid & 31;
    int g  = tid >> 5;
    bool v1 = (g + 8 < m1t2), v2 = (g + 16 < m1t2);
    float ar0 = 0.f, ai0 = 0.f, ar1 = 0.f, ai1 = 0.f, ar2 = 0.f, ai2 = 0.f;
    int N2 = BCm2 * 2;

    for (int h0 = 0; h0 < H; h0 += 64) {
        for (int l = tid; l < 64 * 16; l += 256) {
            int hh = l >> 4, c4 = (l & 15) * 4;
            *(float4*)&xs[hh][c4] =
                *(const float4*)(g_XW + (size_t)(h0 + hh) * N2 + cc0 * 2 + c4);
        }
        for (int l = tid; l < 64 * m1t2 * 2; l += 256) {
            int hh = l / (m1t2 * 2), c = l % (m1t2 * 2);
            tws[hh][c] = tw[(size_t)(h0 + hh) * m1t2 * 2 + c];
        }
        __syncthreads();
        #pragma unroll 4
        for (int hh = 0; hh < 64; hh++) {
            float2 xv = *(const float2*)&xs[hh][2 * cl];
            float tr = tws[hh][2 * g], ti = tws[hh][2 * g + 1];
            ar0 += xv.x * tr - xv.y * ti;
            ai0 += xv.x * ti + xv.y * tr;
            if (v1) {
                float tr1 = tws[hh][2 * (g + 8)], ti1 = tws[hh][2 * (g + 8) + 1];
                ar1 += xv.x * tr1 - xv.y * ti1;
                ai1 += xv.x * ti1 + xv.y * tr1;
            }
            if (v2) {
                float tr2 = tws[hh][2 * (g + 16)], ti2 = tws[hh][2 * (g + 16) + 1];
                ar2 += xv.x * tr2 - xv.y * ti2;
                ai2 += xv.x * ti2 + xv.y * tr2;
            }
        }
        __syncthreads();
    }
    int cc = cc0 + cl, bc = cc / m2, kw = cc % m2;
    size_t oo = (((size_t)bc * m1t2 + g) * m2 + kw) * 2;
    g_XF[oo] = ar0; g_XF[oo + 1] = ai0;
    if (v1) { oo = (((size_t)bc * m1t2 + g + 8) * m2 + kw) * 2;  g_XF[oo] = ar1; g_XF[oo + 1] = ai1; }
    if (v2) { oo = (((size_t)bc * m1t2 + g + 16) * m2 + kw) * 2; g_XF[oo] = ar2; g_XF[oo + 1] = ai2; }
}

// ------- per-mode channel mix -------------------------------------------------
__global__ void k_mix(int Ci, int Co, int m1, int m2,
                      const float* __restrict__ w1, const float* __restrict__ w2) {
    __shared__ float xf_s[3840];
    int m1t2 = 2 * m1, m2c = 2 * m2;
    int kk = blockIdx.x % m1t2;
    int b  = blockIdx.x / m1t2;
    int tid = threadIdx.x;

    for (int l = tid; l < Ci * m2c; l += 256) {
        int i = l / m2c, kc = l % m2c;
        xf_s[l] = g_XF[(((size_t)(b * Ci + i) * m1t2 + kk) * m2) * 2 + kc];
    }
    __syncthreads();

    int kkr = (kk < m1) ? kk : kk - m1;
    const float* wsel = (kk < m1) ? w1 : w2;
    int wstride = Co * m1 * m2 * 2;
    int nout = Co * m2;
    for (int e0 = tid; e0 < nout; e0 += 1024) {
        float orr[4] = {0,0,0,0}, oii[4] = {0,0,0,0};
        int xoff[4], woff[4]; bool val[4];
        #pragma unroll
        for (int u = 0; u < 4; u++) {
            int e = e0 + 256 * u;
            val[u] = (e < nout);
            int kw = val[u] ? e % m2 : 0;
            int o  = val[u] ? e / m2 : 0;
            xoff[u] = 2 * kw;
            woff[u] = ((o * m1 + kkr) * m2 + kw) * 2;
        }
        for (int i = 0; i < Ci; i++) {
            const float* wrow = wsel + (size_t)i * wstride;
            const float* xrow = xf_s + i * m2c;
            #pragma unroll
            for (int u = 0; u < 4; u++) {
                float xr = xrow[xoff[u]], xi = xrow[xoff[u] + 1];
                float wr = wrow[woff[u]], wi = wrow[woff[u] + 1];
                orr[u] += xr * wr - xi * wi;
                oii[u] += xr * wi + xi * wr;
            }
        }
        #pragma unroll
        for (int u = 0; u < 4; u++) {
            if (val[u]) {
                int e = e0 + 256 * u;
                int kw = e % m2, o = e / m2;
                size_t oo = (((size_t)(b * Co + o) * m1t2 + kk) * m2 + kw) * 2;
                g_OF[oo] = orr[u]; g_OF[oo + 1] = oii[u];
            }
        }
    }
}

// ------- inverse DFT along H ---------------------------------------------------
__global__ void k_inv_h(int H, int m1, int m2, const float* __restrict__ tw,
                        float invHW) {
    __shared__ float of_s[1152];
    int bo = blockIdx.x;
    int tid = threadIdx.x;
    int m1t2 = 2 * m1;
    int nload = m1t2 * m2 * 2;
    const float* src = g_OF + (size_t)bo * nload;
    for (int l = tid; l < nload; l += 256) of_s[l] = src[l];
    __syncthreads();

    int nout = H * m2;
    for (int e = tid; e < nout; e += 512) {
        int e2 = e + 256;
        bool v2 = (e2 < nout);
        int kw0 = e % m2, h0 = e / m2;
        int kw1 = v2 ? e2 % m2 : 0, h1 = v2 ? e2 / m2 : 0;
        float zr0 = 0.f, zi0 = 0.f, zr1 = 0.f, zi1 = 0.f;
        for (int kk = 0; kk < m1t2; kk++) {
            float tr0 = tw[(h0 * m1t2 + kk) * 2], ti0 = tw[(h0 * m1t2 + kk) * 2 + 1];
            float fr0 = of_s[(kk * m2 + kw0) * 2], fi0 = of_s[(kk * m2 + kw0) * 2 + 1];
            zr0 += fr0 * tr0 + fi0 * ti0;
            zi0 += fi0 * tr0 - fr0 * ti0;
            float tr1 = tw[(h1 * m1t2 + kk) * 2], ti1 = tw[(h1 * m1t2 + kk) * 2 + 1];
            float fr1 = of_s[(kk * m2 + kw1) * 2], fi1 = of_s[(kk * m2 + kw1) * 2 + 1];
            zr1 += fr1 * tr1 + fi1 * ti1;
            zi1 += fi1 * tr1 - fr1 * ti1;
        }
        size_t oo = ((size_t)bo * nout + e) * 2;
        g_Z[oo] = zr0 * invHW; g_Z[oo + 1] = zi0 * invHW;
        if (v2) {
            oo = ((size_t)bo * nout + e2) * 2;
            g_Z[oo] = zr1 * invHW; g_Z[oo + 1] = zi1 * invHW;
        }
    }
}

// ------- fused GEMM: out = gelu(conv1x1 + bias + invW(Z)) --------------------
// tile 64ch x 128px, 4x8 microtile, K-chunk 32, spec folded as K=2m2 GEMM prime
__global__ void k_fuse(const float* __restrict__ xin, int Ci, int Co,
                       int H, int W, int m2, const float* __restrict__ tw,
                       const float* __restrict__ cw, const float* __restrict__ cb,
                       float* __restrict__ out, int Ct, int coff) {
    __shared__ float xs[32][132];
    __shared__ float wst[32][68];
    __shared__ float zst[1536];          // [nplanes][m2c][64]
    __shared__ float twst[24][128];

    const int HW = H * W;
    int tilesPerImg = HW >> 7;
    int b  = blockIdx.x / tilesPerImg;
    int p0 = (blockIdx.x % tilesPerImg) << 7;
    int ob = blockIdx.y << 6;
    int h0 = p0 / W, w0 = p0 % W;
    int tid = threadIdx.x;
    int ty = tid >> 4, tx = tid & 15;
    int m2c = 2 * m2;
    int nplanes = (W == 64) ? 2 : 1;

    // stage spectral operands
    for (int l = tid; l < nplanes * m2c * 64; l += 256) {
        int q = l / (m2c * 64);
        int rem = l - q * m2c * 64;
        int r = rem >> 6, o = rem & 63;
        int oo = ob + o;
        float v = (oo < Co) ? g_Z[(((size_t)(b * Co + oo) * H + h0 + q) * m2) * 2 + r] : 0.f;
        zst[l] = (r >= 2) ? 2.0f * v : v;
    }
    for (int l = tid; l < m2c * 128; l += 256) {
        int r = l >> 7, p = l & 127;
        twst[r][p] = tw[(size_t)((w0 + p) % W) * m2c + r];
    }
    __syncthreads();

    float acc[4][8];
    #pragma unroll
    for (int r = 0; r < 4; r++)
        #pragma unroll
        for (int c = 0; c < 8; c++) acc[r][c] = 0.f;

    // spectral prime: K = m2c
    int zbase = (W == 64) ? ((tx >> 3) * m2c * 64) : 0;
    for (int r = 0; r < m2c; r++) {
        float4 zv = *(const float4*)&zst[zbase + r * 64 + ty * 4];
        float4 t0 = *(const float4*)&twst[r][tx * 8];
        float4 t1 = *(const float4*)&twst[r][tx * 8 + 4];
        acc[0][0] += zv.x * t0.x; acc[0][1] += zv.x * t0.y; acc[0][2] += zv.x * t0.z; acc[0][3] += zv.x * t0.w;
        acc[0][4] += zv.x * t1.x; acc[0][5] += zv.x * t1.y; acc[0][6] += zv.x * t1.z; acc[0][7] += zv.x * t1.w;
        acc[1][0] += zv.y * t0.x; acc[1][1] += zv.y * t0.y; acc[1][2] += zv.y * t0.z; acc[1][3] += zv.y * t0.w;
        acc[1][4] += zv.y * t1.x; acc[1][5] += zv.y * t1.y; acc[1][6] += zv.y * t1.z; acc[1][7] += zv.y * t1.w;
        acc[2][0] += zv.z * t0.x; acc[2][1] += zv.z * t0.y; acc[2][2] += zv.z * t0.z; acc[2][3] += zv.z * t0.w;
        acc[2][4] += zv.z * t1.x; acc[2][5] += zv.z * t1.y; acc[2][6] += zv.z * t1.z; acc[2][7] += zv.z * t1.w;
        acc[3][0] += zv.w * t0.x; acc[3][1] += zv.w * t0.y; acc[3][2] += zv.w * t0.z; acc[3][3] += zv.w * t0.w;
        acc[3][4] += zv.w * t1.x; acc[3][5] += zv.w * t1.y; acc[3][6] += zv.w * t1.z; acc[3][7] += zv.w * t1.w;
    }

    // conv1x1 main loop: K chunks of 32
    for (int ci0 = 0; ci0 < Ci; ci0 += 32) {
        __syncthreads();
        for (int l = tid; l < 1024; l += 256) {
            int i = l >> 5, p4 = (l & 31) * 4;
            *(float4*)&xs[i][p4] =
                *(const float4*)(xin + (size_t)(b * Ci + ci0 + i) * HW + p0 + p4);
        }
        for (int l = tid; l < 512; l += 256) {
            int o = l >> 3, i4 = (l & 7) * 4;
            int oo = ob + o;
            float4 wv = (oo < Co) ? *(const float4*)(cw + (size_t)oo * Ci + ci0 + i4)
                                  : make_float4(0.f, 0.f, 0.f, 0.f);
            wst[i4][o] = wv.x; wst[i4 + 1][o] = wv.y;
            wst[i4 + 2][o] = wv.z; wst[i4 + 3][o] = wv.w;
        }
        __syncthreads();
        #pragma unroll
        for (int i = 0; i < 32; i++) {
            float4 wv = *(const float4*)&wst[i][ty * 4];
            float4 x0 = *(const float4*)&xs[i][tx * 8];
            float4 x1 = *(const float4*)&xs[i][tx * 8 + 4];
            acc[0][0] += wv.x * x0.x; acc[0][1] += wv.x * x0.y; acc[0][2] += wv.x * x0.z; acc[0][3] += wv.x * x0.w;
            acc[0][4] += wv.x * x1.x; acc[0][5] += wv.x * x1.y; acc[0][6] += wv.x * x1.z; acc[0][7] += wv.x * x1.w;
            acc[1][0] += wv.y * x0.x; acc[1][1] += wv.y * x0.y; acc[1][2] += wv.y * x0.z; acc[1][3] += wv.y * x0.w;
            acc[1][4] += wv.y * x1.x; acc[1][5] += wv.y * x1.y; acc[1][6] += wv.y * x1.z; acc[1][7] += wv.y * x1.w;
            acc[2][0] += wv.z * x0.x; acc[2][1] += wv.z * x0.y; acc[2][2] += wv.z * x0.z; acc[2][3] += wv.z * x0.w;
            acc[2][4] += wv.z * x1.x; acc[2][5] += wv.z * x1.y; acc[2][6] += wv.z * x1.z; acc[2][7] += wv.z * x1.w;
            acc[3][0] += wv.w * x0.x; acc[3][1] += wv.w * x0.y; acc[3][2] += wv.w * x0.z; acc[3][3] += wv.w * x0.w;
            acc[3][4] += wv.w * x1.x; acc[3][5] += wv.w * x1.y; acc[3][6] += wv.w * x1.z; acc[3][7] += wv.w * x1.w;
        }
    }

    #pragma unroll
    for (int r = 0; r < 4; r++) {
        int oo = ob + ty * 4 + r;
        if (oo >= Co) continue;
        float bias = cb[oo];
        float res[8];
        #pragma unroll
        for (int c = 0; c < 8; c++) res[c] = gelu_f(acc[r][c] + bias);
        float* op = out + (size_t)(b * Ct + coff + oo) * HW + p0 + tx * 8;
        *(float4*)op = make_float4(res[0], res[1], res[2], res[3]);
        *(float4*)(op + 4) = make_float4(res[4], res[5], res[6], res[7]);
    }
}

// ---------------- 2x2 mean pool (strided channel source) ---------------------
__global__ void k_pool(const float* __restrict__ in, int total, int C, int Ct, int coff,
                       int H, int W, float* __restrict__ out) {
    int idx = blockIdx.x * blockDim.x + threadIdx.x;
    if (idx >= total) return;
    int Ho = H / 2, Wo = W / 2;
    int wo = idx % Wo;
    int ho = (idx / Wo) % Ho;
    int c  = (idx / (Wo * Ho)) % C;
    int b  = idx / (Wo * Ho * C);
    const float* p = in + ((size_t)(b * Ct + coff + c) * H + 2 * ho) * W + 2 * wo;
    out[idx] = 0.25f * (p[0] + p[1] + p[W] + p[W + 1]);
}

// ---------------- bilinear 2x upsample (half-pixel) into concat dst ----------
__global__ void k_up(const float* __restrict__ in, int total, int C, int H, int W,
                     float* __restrict__ dst, int Ct, int coff) {
    int idx = blockIdx.x * blockDim.x + threadIdx.x;
    if (idx >= total) return;
    int Ho = 2 * H, Wo = 2 * W;
    int wo = idx % Wo;
    int ho = (idx / Wo) % Ho;
    int c  = (idx / (Wo * Ho)) % C;
    int b  = idx / (Wo * Ho * C);

    int kh = ho >> 1, ha, hb; float wha, whb;
    if (ho & 1) { ha = kh; hb = (kh + 1 < H) ? kh + 1 : H - 1; wha = 0.75f; whb = 0.25f; }
    else        { ha = (kh - 1 >= 0) ? kh - 1 : 0; hb = kh;    wha = 0.25f; whb = 0.75f; }
    int kw = wo >> 1, wa, wb; float wwa, wwb;
    if (wo & 1) { wa = kw; wb = (kw + 1 < W) ? kw + 1 : W - 1; wwa = 0.75f; wwb = 0.25f; }
    else        { wa = (kw - 1 >= 0) ? kw - 1 : 0; wb = kw;    wwa = 0.25f; wwb = 0.75f; }

    const float* base = in + (size_t)(b * C + c) * H * W;
    float v = wha * (wwa * base[(size_t)ha * W + wa] + wwb * base[(size_t)ha * W + wb])
            + whb * (wwa * base[(size_t)hb * W + wa] + wwb * base[(size_t)hb * W + wb]);
    dst[((size_t)(b * Ct + coff + c) * Ho + ho) * Wo + wo] = v;
}

// ------- head: 64px x 256o per block; x resident; shfl fc2 reduction ---------
__global__ void k_head(const float* __restrict__ xin, const float* __restrict__ w1,
                       const float* __restrict__ b1, const float* __restrict__ w2,
                       const float* __restrict__ b2, float* __restrict__ out) {
    __shared__ float xs[64][68];
    __shared__ float wst[32][132];

    const int HW = 256 * 256;
    int b  = blockIdx.x >> 10;
    int p0 = (blockIdx.x & 1023) << 6;
    int tid = threadIdx.x;
    int ty = tid >> 4, tx = tid & 15;     // ty: px group (4 px), tx: o group (8 o)

    for (int l = tid; l < 1024; l += 256) {
        int i = l >> 4, p4 = (l & 15) * 4;
        *(float4*)&xs[i][p4] =
            *(const float4*)(xin + (size_t)(b * 64 + i) * HW + p0 + p4);
    }

    float o3[3][4];
    #pragma unroll
    for (int cc = 0; cc < 3; cc++)
        #pragma unroll
        for (int r = 0; r < 4; r++) o3[cc][r] = 0.f;

    for (int oc = 0; oc < 2; oc++) {
        float acc[4][8];
        #pragma unroll
        for (int c = 0; c < 8; c++) {
            float bb = b1[oc * 128 + tx * 8 + c];
            #pragma unroll
            for (int r = 0; r < 4; r++) acc[r][c] = bb;
        }
        for (int i0 = 0; i0 < 64; i0 += 32) {
            __syncthreads();
            for (int l = tid; l < 1024; l += 256) {
                int o = l >> 3, i4 = (l & 7) * 4;
                float4 wv = *(const float4*)(w1 + (size_t)(oc * 128 + o) * 64 + i0 + i4);
                wst[i4][o] = wv.x; wst[i4 + 1][o] = wv.y;
                wst[i4 + 2][o] = wv.z; wst[i4 + 3][o] = wv.w;
            }
            __syncthreads();
            #pragma unroll
            for (int i = 0; i < 32; i++) {
                float4 xv = *(const float4*)&xs[i0 + i][ty * 4];
                float4 w0v = *(const float4*)&wst[i][tx * 8];
                float4 w1v = *(const float4*)&wst[i][tx * 8 + 4];
                acc[0][0] += xv.x * w0v.x; acc[0][1] += xv.x * w0v.y; acc[0][2] += xv.x * w0v.z; acc[0][3] += xv.x * w0v.w;
                acc[0][4] += xv.x * w1v.x; acc[0][5] += xv.x * w1v.y; acc[0][6] += xv.x * w1v.z; acc[0][7] += xv.x * w1v.w;
                acc[1][0] += xv.y * w0v.x; acc[1][1] += xv.y * w0v.y; acc[1][2] += xv.y * w0v.z; acc[1][3] += xv.y * w0v.w;
                acc[1][4] += xv.y * w1v.x; acc[1][5] += xv.y * w1v.y; acc[1][6] += xv.y * w1v.z; acc[1][7] += xv.y * w1v.w;
                acc[2][0] += xv.z * w0v.x; acc[2][1] += xv.z * w0v.y; acc[2][2] += xv.z * w0v.z; acc[2][3] += xv.z * w0v.w;
                acc[2][4] += xv.z * w1v.x; acc[2][5] += xv.z * w1v.y; acc[2][6] += xv.z * w1v.z; acc[2][7] += xv.z * w1v.w;
                acc[3][0] += xv.w * w0v.x; acc[3][1] += xv.w * w0v.y; acc[3][2] += xv.w * w0v.z; acc[3][3] += xv.w * w0v.w;
                acc[3][4] += xv.w * w1v.x; acc[3][5] += xv.w * w1v.y; acc[3][6] += xv.w * w1v.z; acc[3][7] += xv.w * w1v.w;
            }
        }
        #pragma unroll
        for (int c = 0; c < 8; c++) {
            int o = oc * 128 + tx * 8 + c;
            float w20 = w2[o], w21 = w2[256 + o], w22 = w2[512 + o];
            #pragma unroll
            for (int r = 0; r < 4; r++) {
                float hh = gelu_f(acc[r][c]);
                o3[0][r] += hh * w20;
                o3[1][r] += hh * w21;
                o3[2][r] += hh * w22;
            }
        }
    }

    // reduce over tx (16 threads share same px set) via shfl, width 16
    #pragma unroll
    for (int cc = 0; cc < 3; cc++)
        #pragma unroll
        for (int r = 0; r < 4; r++) {
            float v = o3[cc][r];
            v += __shfl_down_sync(0xffffffffu, v, 8, 16);
            v += __shfl_down_sync(0xffffffffu, v, 4, 16);
            v += __shfl_down_sync(0xffffffffu, v, 2, 16);
            v += __shfl_down_sync(0xffffffffu, v, 1, 16);
            o3[cc][r] = v;
        }
    if (tx == 0) {
        #pragma unroll
        for (int r = 0; r < 4; r++) {
            size_t pp = (size_t)b * HW + p0 + ty * 4 + r;
            out[pp * 3 + 0] = o3[0][r] + b2[0];
            out[pp * 3 + 1] = o3[1][r] + b2[1];
            out[pp * 3 + 2] = o3[2][r] + b2[2];
        }
    }
}

// =============================================================================
static inline int grid_of(int total) { return (total + 255) / 256; }

static void spectral_block(const float* xin, int Ci, int Co, int H, int m1,
                           const float* w1, const float* w2,
                           const float* cw, const float* cb,
                           const float* twW, const float* twH,
                           float* out, int Ct, int coff) {
    const int W = H, m2 = m1, m1t2 = 2 * m1;
    int BC = BSZ * Ci;
    k_fwd_w<<<BC * H / 64, 256>>>(xin, H, W, m2, twW, BC);
    k_fwd_h<<<BC * m2 / 32, 256>>>(H, BC * m2, m1, m2, twH);
    k_mix<<<BSZ * m1t2, 256>>>(Ci, Co, m1, m2, w1, w2);
    k_inv_h<<<BSZ * Co, 256>>>(H, m1, m2, twH, 1.0f / (float)(H * W));
    dim3 fg(BSZ * H * W / 128, (Co + 63) / 64);
    k_fuse<<<fg, 256>>>(xin, Ci, Co, H, W, m2, twW, cw, cb, out, Ct, coff);
}

extern "C" void kernel_launch(void* const* d_in, const int* in_sizes, int n_in,
                              void* d_out, int out_size) {
    const float* x      = (const float*)d_in[0];
    const float* fcin_w = (const float*)d_in[1];
    const float* fcin_b = (const float*)d_in[2];
    const float* sc1_w1 = (const float*)d_in[3];
    const float* sc1_w2 = (const float*)d_in[4];
    const float* c1_w   = (const float*)d_in[5];
    const float* c1_b   = (const float*)d_in[6];
    const float* sc2_w1 = (const float*)d_in[7];
    const float* sc2_w2 = (const float*)d_in[8];
    const float* c2_w   = (const float*)d_in[9];
    const float* c2_b   = (const float*)d_in[10];
    const float* scb_w1 = (const float*)d_in[11];
    const float* scb_w2 = (const float*)d_in[12];
    const float* cb_w   = (const float*)d_in[13];
    const float* cb_b   = (const float*)d_in[14];
    const float* su2_w1 = (const float*)d_in[15];
    const float* su2_w2 = (const float*)d_in[16];
    const float* u2_w   = (const float*)d_in[17];
    const float* u2_b   = (const float*)d_in[18];
    const float* su1_w1 = (const float*)d_in[19];
    const float* su1_w2 = (const float*)d_in[20];
    const float* u1_w   = (const float*)d_in[21];
    const float* u1_b   = (const float*)d_in[22];
    const float* fc1_w  = (const float*)d_in[23];
    const float* fc1_b  = (const float*)d_in[24];
    const float* fc2_w  = (const float*)d_in[25];
    const float* fc2_b  = (const float*)d_in[26];

    float *p_v, *p_x1d, *p_x2d, *p_xb, *p_x2c, *p_x2o, *p_x1c, *p_x1o, *p_tw;
    cudaGetSymbolAddress((void**)&p_v,   g_v);
    cudaGetSymbolAddress((void**)&p_x1d, g_x1d);
    cudaGetSymbolAddress((void**)&p_x2d, g_x2d);
    cudaGetSymbolAddress((void**)&p_xb,  g_xb);
    cudaGetSymbolAddress((void**)&p_x2c, g_x2c);
    cudaGetSymbolAddress((void**)&p_x2o, g_x2o);
    cudaGetSymbolAddress((void**)&p_x1c, g_x1c);
    cudaGetSymbolAddress((void**)&p_x1o, g_x1o);
    cudaGetSymbolAddress((void**)&p_tw,  g_tw);

    const float* tw_W0 = p_tw + 2 * TW0;
    const float* tw_H0 = p_tw + 2 * TH0;
    const float* tw_W1 = p_tw + 2 * TW1;
    const float* tw_H1 = p_tw + 2 * TH1;
    const float* tw_W2 = p_tw + 2 * TW2;
    const float* tw_H2 = p_tw + 2 * TH2;

    k_init_tw<<<32, 256>>>();

    // lift 6 -> 64 (tiled)
    k_lift<<<BSZ * 1024, 256>>>(x, fcin_w, fcin_b);

    // encoder level 1: 64 -> 64 @ 256 ; x1 written directly into x1c[96:160]
    spectral_block(p_v, 64, 64, 256, 12, sc1_w1, sc1_w2, c1_w, c1_b, tw_W0, tw_H0,
                   p_x1c, 160, 96);
    {
        int t = BSZ * 64 * 128 * 128;
        k_pool<<<grid_of(t), 256>>>(p_x1c, t, 64, 160, 96, 256, 256, p_x1d);
    }

    // encoder level 2: 64 -> 96 @ 128 ; x2 written into x2c[128:224]
    spectral_block(p_x1d, 64, 96, 128, 8, sc2_w1, sc2_w2, c2_w, c2_b, tw_W1, tw_H1,
                   p_x2c, 224, 128);
    {
        int t = BSZ * 96 * 64 * 64;
        k_pool<<<grid_of(t), 256>>>(p_x2c, t, 96, 224, 128, 128, 128, p_x2d);
    }

    // bottleneck: 96 -> 128 @ 64
    spectral_block(p_x2d, 96, 128, 64, 4, scb_w1, scb_w2, cb_w, cb_b, tw_W2, tw_H2,
                   p_xb, 128, 0);

    // up(xb) -> x2c[0:128]
    {
        int t = BSZ * 128 * 128 * 128;
        k_up<<<grid_of(t), 256>>>(p_xb, t, 128, 64, 64, p_x2c, 224, 0);
    }

    // decoder level 2: 224 -> 96 @ 128
    spectral_block(p_x2c, 224, 96, 128, 8, su2_w1, su2_w2, u2_w, u2_b, tw_W1, tw_H1,
                   p_x2o, 96, 0);

    // up(x2o) -> x1c[0:96]
    {
        int t = BSZ * 96 * 256 * 256;
        k_up<<<grid_of(t), 256>>>(p_x2o, t, 96, 128, 128, p_x1c, 160, 0);
    }

    // decoder level 1: 160 -> 64 @ 256
    spectral_block(p_x1c, 160, 64, 256, 12, su1_w1, su1_w2, u1_w, u1_b, tw_W0, tw_H0,
                   p_x1o, 64, 0);

    // head
    k_head<<<BSZ * 1024, 256>>>(p_x1o, fc1_w, fc1_b, fc2_w, fc2_b, (float*)d_out);
}

// round 8
// speedup vs baseline: 1.1160x; 1.1160x over previous
#include <cuda_runtime.h>
#include <math.h>

#define BSZ 4

// ---------------- scratch (device globals; no allocations allowed) ----------
__device__ float g_v  [16777216];   // [4,64,256,256]
__device__ float g_x1d[ 4194304];   // [4,64,128,128]
__device__ float g_x2d[ 1572864];   // [4,96,64,64]
__device__ float g_xb [ 2097152];   // [4,128,64,64]
__device__ float g_x2c[14680064];   // [4,224,128,128] (x2 at coff 128)
__device__ float g_x2o[ 6291456];   // [4,96,128,128]
__device__ float g_x1c[41943040];   // [4,160,256,256] (x1 at coff 96)
__device__ float g_x1o[16777216];   // [4,64,256,256]

__device__ float g_XW [ 3932160];   // transposed: [H][BC*m2c]
__device__ float g_XF [  368640];   // [BC,2m1,m2] complex
__device__ float g_OF [  368640];   // [B,Co,2m1,m2] complex
__device__ float g_Z  [ 1572864];   // [B,Co,H,m2] complex (scaled)
__device__ float g_tw [   26112];   // twiddle tables (complex interleaved)

#define TW0 0
#define TH0 3072
#define TW1 9216
#define TH1 10240
#define TW2 12288
#define TH2 12544

__device__ __forceinline__ float gelu_f(float x) {
    return 0.5f * x * (1.0f + erff(x * 0.70710678118654752f));
}

// ---------------- twiddle init -----------------------------------------------
__global__ void k_init_tw() {
    const int cfg[3][5] = {{256,12,12,TW0,TH0},{128,8,8,TW1,TH1},{64,4,4,TW2,TH2}};
    int tid = blockIdx.x * blockDim.x + threadIdx.x;
    int nth = gridDim.x * blockDim.x;
    for (int c = 0; c < 3; c++) {
        int H = cfg[c][0], m1 = cfg[c][1], m2 = cfg[c][2];
        int offW = cfg[c][3], offH = cfg[c][4];
        int nW = H * m2;
        for (int e = tid; e < nW; e += nth) {
            int w = e / m2, kw = e % m2;
            int p = (w * kw) % H;
            double s, co; sincos(2.0 * 3.14159265358979323846 * (double)p / (double)H, &s, &co);
            g_tw[(offW + e) * 2]     = (float)co;
            g_tw[(offW + e) * 2 + 1] = (float)(-s);
        }
        int m1t2 = 2 * m1;
        int nH = H * m1t2;
        for (int e = tid; e < nH; e += nth) {
            int h = e / m1t2, j = e % m1t2;
            int kh = (j < m1) ? j : (H - 2 * m1 + j);
            int p = (kh * h) % H;
            double s, co; sincos(2.0 * 3.14159265358979323846 * (double)p / (double)H, &s, &co);
            g_tw[(offH + e) * 2]     = (float)co;
            g_tw[(offH + e) * 2 + 1] = (float)(-s);
        }
    }
}

// ---------------- lift: x[B,H,W,6] -> v[B,64,H,W] ----------------------------
__global__ void k_lift(const float* __restrict__ x, const float* __restrict__ w,
                       const float* __restrict__ b) {
    const int HW = 256 * 256;
    int idx = blockIdx.x * blockDim.x + threadIdx.x;
    if (idx >= BSZ * 64 * HW) return;
    int p  = idx % HW;
    int c  = (idx / HW) % 64;
    int bb = idx / (HW * 64);
    const float* xp = x + ((size_t)bb * HW + p) * 6;
    float acc = b[c];
    #pragma unroll
    for (int i = 0; i < 6; i++) acc += xp[i] * w[c * 6 + i];
    g_v[idx] = acc;
}

// ------- fwd DFT along W: x rows -> XWt[h][bc*m2c] (transposed) -------------
__global__ void k_fwd_w(const float* __restrict__ xin, int H, int W, int m2,
                        const float* __restrict__ tw, int BC) {
    __shared__ float xs[64][68];
    __shared__ float tws[64][24];
    int m2c = 2 * m2;
    int r0 = blockIdx.x * 64;
    int tid = threadIdx.x;
    int row_l = tid & 31;
    int kc0 = tid >> 5;
    bool v1 = (kc0 + 8 < m2c), v2 = (kc0 + 16 < m2c);
    float a00 = 0.f, a01 = 0.f, a02 = 0.f, a10 = 0.f, a11 = 0.f, a12 = 0.f;

    for (int k0 = 0; k0 < W; k0 += 64) {
        for (int l = tid; l < 64 * 16; l += 256) {
            int r = l >> 4, k4 = (l & 15) * 4;
            float4 v = *(const float4*)(xin + (size_t)(r0 + r) * W + k0 + k4);
            *(float4*)&xs[r][k4] = v;
        }
        for (int l = tid; l < 64 * m2c; l += 256) {
            int k = l / m2c, kc = l % m2c;
            tws[k][kc] = tw[(size_t)(k0 + k) * m2c + kc];
        }
        __syncthreads();
        #pragma unroll 4
        for (int k = 0; k < 64; k++) {
            float x0 = xs[row_l][k];
            float x1 = xs[row_l + 32][k];
            float t0 = tws[k][kc0];
            a00 += x0 * t0; a10 += x1 * t0;
            if (v1) { float t1 = tws[k][kc0 + 8];  a01 += x0 * t1; a11 += x1 * t1; }
            if (v2) { float t2 = tws[k][kc0 + 16]; a02 += x0 * t2; a12 += x1 * t2; }
        }
        __syncthreads();
    }
    int r = r0 + row_l;
    int bc = r / H, h = r - bc * H;
    size_t base = ((size_t)h * BC + bc) * m2c;
    g_XW[base + kc0] = a00;
    if (v1) g_XW[base + kc0 + 8]  = a01;
    if (v2) g_XW[base + kc0 + 16] = a02;
    r = r0 + row_l + 32;
    bc = r / H; h = r - bc * H;
    base = ((size_t)h * BC + bc) * m2c;
    g_XW[base + kc0] = a10;
    if (v1) g_XW[base + kc0 + 8]  = a11;
    if (v2) g_XW[base + kc0 + 16] = a12;
}

// ------- fwd DFT along H: 256 threads, 16 complex cols per block -------------
// grid = BCm2/16 (2x wider than before); thread: 1 col x up to 2 modes.
__global__ void k_fwd_h(int H, int BCm2, int m1, int m2, const float* __restrict__ tw) {
    __shared__ float xs[64][32];
    __shared__ float tws[64][48];
    int m1t2 = 2 * m1;
    int cc0 = blockIdx.x * 16;
    int tid = threadIdx.x;
    int cl = tid & 15;
    int g  = tid >> 4;          // 0..15
    bool v0 = (g < m1t2);
    bool v1 = (g + 16 < m1t2);
    float ar0 = 0.f, ai0 = 0.f, ar1 = 0.f, ai1 = 0.f;
    int N2 = BCm2 * 2;

    for (int h0 = 0; h0 < H; h0 += 64) {
        for (int l = tid; l < 64 * 8; l += 256) {
            int hh = l >> 3, c4 = (l & 7) * 4;
            *(float4*)&xs[hh][c4] =
                *(const float4*)(g_XW + (size_t)(h0 + hh) * N2 + cc0 * 2 + c4);
        }
        for (int l = tid; l < 64 * m1t2 * 2; l += 256) {
            int hh = l / (m1t2 * 2), c = l % (m1t2 * 2);
            tws[hh][c] = tw[(size_t)(h0 + hh) * m1t2 * 2 + c];
        }
        __syncthreads();
        #pragma unroll 4
        for (int hh = 0; hh < 64; hh++) {
            float2 xv = *(const float2*)&xs[hh][2 * cl];
            if (v0) {
                float tr = tws[hh][2 * g], ti = tws[hh][2 * g + 1];
                ar0 += xv.x * tr - xv.y * ti;
                ai0 += xv.x * ti + xv.y * tr;
            }
            if (v1) {
                float tr1 = tws[hh][2 * (g + 16)], ti1 = tws[hh][2 * (g + 16) + 1];
                ar1 += xv.x * tr1 - xv.y * ti1;
                ai1 += xv.x * ti1 + xv.y * tr1;
            }
        }
        __syncthreads();
    }
    int cc = cc0 + cl, bc = cc / m2, kw = cc % m2;
    if (v0) {
        size_t oo = (((size_t)bc * m1t2 + g) * m2 + kw) * 2;
        g_XF[oo] = ar0; g_XF[oo + 1] = ai0;
    }
    if (v1) {
        size_t oo = (((size_t)bc * m1t2 + g + 16) * m2 + kw) * 2;
        g_XF[oo] = ar1; g_XF[oo + 1] = ai1;
    }
}

// ------- per-mode channel mix; Co split over blockIdx.y -----------------------
__global__ void k_mix(int Ci, int Co, int m1, int m2,
                      const float* __restrict__ w1, const float* __restrict__ w2) {
    __shared__ float xf_s[3840];
    int m1t2 = 2 * m1, m2c = 2 * m2;
    int kk = blockIdx.x % m1t2;
    int b  = blockIdx.x / m1t2;
    int oy = blockIdx.y;
    int tid = threadIdx.x;

    for (int l = tid; l < Ci * m2c; l += 256) {
        int i = l / m2c, kc = l % m2c;
        xf_s[l] = g_XF[(((size_t)(b * Ci + i) * m1t2 + kk) * m2) * 2 + kc];
    }
    __syncthreads();

    int kkr = (kk < m1) ? kk : kk - m1;
    const float* wsel = (kk < m1) ? w1 : w2;
    int wstride = Co * m1 * m2 * 2;
    int nout = Co * m2;
    int half = nout >> 1;                        // Co*m2 always even
    int e_begin = oy * half;
    int e_end   = e_begin + half;
    for (int e0 = e_begin + tid; e0 < e_end; e0 += 1024) {
        float orr[4] = {0,0,0,0}, oii[4] = {0,0,0,0};
        int xoff[4], woff[4]; bool val[4];
        #pragma unroll
        for (int u = 0; u < 4; u++) {
            int e = e0 + 256 * u;
            val[u] = (e < e_end);
            int kw = val[u] ? e % m2 : 0;
            int o  = val[u] ? e / m2 : 0;
            xoff[u] = 2 * kw;
            woff[u] = ((o * m1 + kkr) * m2 + kw) * 2;
        }
        for (int i = 0; i < Ci; i++) {
            const float* wrow = wsel + (size_t)i * wstride;
            const float* xrow = xf_s + i * m2c;
            #pragma unroll
            for (int u = 0; u < 4; u++) {
                float xr = xrow[xoff[u]], xi = xrow[xoff[u] + 1];
                float wr = wrow[woff[u]], wi = wrow[woff[u] + 1];
                orr[u] += xr * wr - xi * wi;
                oii[u] += xr * wi + xi * wr;
            }
        }
        #pragma unroll
        for (int u = 0; u < 4; u++) {
            if (val[u]) {
                int e = e0 + 256 * u;
                int kw = e % m2, o = e / m2;
                size_t oo = (((size_t)(b * Co + o) * m1t2 + kk) * m2 + kw) * 2;
                g_OF[oo] = orr[u]; g_OF[oo + 1] = oii[u];
            }
        }
    }
}

// ------- inverse DFT along H ---------------------------------------------------
__global__ void k_inv_h(int H, int m1, int m2, const float* __restrict__ tw,
                        float invHW) {
    __shared__ float of_s[1152];
    int bo = blockIdx.x;
    int tid = threadIdx.x;
    int m1t2 = 2 * m1;
    int nload = m1t2 * m2 * 2;
    const float* src = g_OF + (size_t)bo * nload;
    for (int l = tid; l < nload; l += 256) of_s[l] = src[l];
    __syncthreads();

    int nout = H * m2;
    for (int e = tid; e < nout; e += 512) {
        int e2 = e + 256;
        bool v2 = (e2 < nout);
        int kw0 = e % m2, h0 = e / m2;
        int kw1 = v2 ? e2 % m2 : 0, h1 = v2 ? e2 / m2 : 0;
        float zr0 = 0.f, zi0 = 0.f, zr1 = 0.f, zi1 = 0.f;
        for (int kk = 0; kk < m1t2; kk++) {
            float tr0 = tw[(h0 * m1t2 + kk) * 2], ti0 = tw[(h0 * m1t2 + kk) * 2 + 1];
            float fr0 = of_s[(kk * m2 + kw0) * 2], fi0 = of_s[(kk * m2 + kw0) * 2 + 1];
            zr0 += fr0 * tr0 + fi0 * ti0;
            zi0 += fi0 * tr0 - fr0 * ti0;
            float tr1 = tw[(h1 * m1t2 + kk) * 2], ti1 = tw[(h1 * m1t2 + kk) * 2 + 1];
            float fr1 = of_s[(kk * m2 + kw1) * 2], fi1 = of_s[(kk * m2 + kw1) * 2 + 1];
            zr1 += fr1 * tr1 + fi1 * ti1;
            zi1 += fi1 * tr1 - fr1 * ti1;
        }
        size_t oo = ((size_t)bo * nout + e) * 2;
        g_Z[oo] = zr0 * invHW; g_Z[oo + 1] = zi0 * invHW;
        if (v2) {
            oo = ((size_t)bo * nout + e2) * 2;
            g_Z[oo] = zr1 * invHW; g_Z[oo + 1] = zi1 * invHW;
        }
    }
}

// ------- fused GEMM: out = gelu(conv1x1 + bias + invW(Z)) --------------------
// R6-proven: 64 ch x 64 px tile, contiguous 4x4 microtile, K-chunk 32
__global__ void k_fuse(const float* __restrict__ xin, int Ci, int Co,
                       int H, int W, int m2, const float* __restrict__ tw,
                       const float* __restrict__ cw, const float* __restrict__ cb,
                       float* __restrict__ out, int Ct, int coff) {
    __shared__ float xs[32][68];
    __shared__ float wst[32][68];   // [i][o]
    __shared__ float zs[64][25];
    __shared__ float tws[64][25];

    const int HW = H * W;
    int tilesPerImg = HW >> 6;
    int b  = blockIdx.x / tilesPerImg;
    int p0 = (blockIdx.x % tilesPerImg) << 6;
    int ob = blockIdx.y << 6;
    int h  = p0 / W, w0 = p0 % W;
    int tid = threadIdx.x;
    int ty = tid >> 4, tx = tid & 15;

    float acc[4][4];
    #pragma unroll
    for (int r = 0; r < 4; r++)
        #pragma unroll
        for (int c = 0; c < 4; c++) acc[r][c] = 0.f;

    for (int ci0 = 0; ci0 < Ci; ci0 += 32) {
        for (int l = tid; l < 512; l += 256) {
            int i = l >> 4, p4 = (l & 15) * 4;
            float4 v = *(const float4*)(xin + (size_t)(b * Ci + ci0 + i) * HW + p0 + p4);
            *(float4*)&xs[i][p4] = v;
        }
        for (int l = tid; l < 2048; l += 256) {
            int o = l >> 5, i = l & 31;
            int oo = ob + o;
            wst[i][o] = (oo < Co) ? cw[(size_t)oo * Ci + ci0 + i] : 0.f;
        }
        __syncthreads();
        #pragma unroll
        for (int i = 0; i < 32; i++) {
            float4 xv = *(const float4*)&xs[i][tx * 4];
            float4 wv = *(const float4*)&wst[i][ty * 4];
            acc[0][0] += wv.x * xv.x; acc[0][1] += wv.x * xv.y;
            acc[0][2] += wv.x * xv.z; acc[0][3] += wv.x * xv.w;
            acc[1][0] += wv.y * xv.x; acc[1][1] += wv.y * xv.y;
            acc[1][2] += wv.y * xv.z; acc[1][3] += wv.y * xv.w;
            acc[2][0] += wv.z * xv.x; acc[2][1] += wv.z * xv.y;
            acc[2][2] += wv.z * xv.z; acc[2][3] += wv.z * xv.w;
            acc[3][0] += wv.w * xv.x; acc[3][1] += wv.w * xv.y;
            acc[3][2] += wv.w * xv.z; acc[3][3] += wv.w * xv.w;
        }
        __syncthreads();
    }

    int m2c = 2 * m2;
    for (int l = tid; l < 64 * m2c; l += 256) {
        int o = l / m2c, r = l % m2c;
        int oo = ob + o;
        float v = (oo < Co) ? g_Z[(((size_t)(b * Co + oo) * H + h) * m2) * 2 + r] : 0.f;
        zs[o][r] = (r >= 2) ? 2.0f * v : v;
    }
    for (int l = tid; l < 64 * m2c; l += 256) {
        int p = l / m2c, r = l % m2c;
        tws[p][r] = tw[(size_t)(w0 + p) * m2c + r];
    }
    __syncthreads();

    #pragma unroll
    for (int r = 0; r < 4; r++) {
        int o_l = ty * 4 + r;
        int oo = ob + o_l;
        if (oo >= Co) continue;
        float bias = cb[oo];
        float res[4];
        #pragma unroll
        for (int c = 0; c < 4; c++) {
            int p_l = tx * 4 + c;
            float spec = 0.f;
            for (int kw = 0; kw < m2; kw++) {
                spec += zs[o_l][2 * kw] * tws[p_l][2 * kw]
                      + zs[o_l][2 * kw + 1] * tws[p_l][2 * kw + 1];
            }
            res[c] = gelu_f(acc[r][c] + bias + spec);
        }
        *(float4*)(out + (size_t)(b * Ct + coff + oo) * HW + p0 + tx * 4) =
            make_float4(res[0], res[1], res[2], res[3]);
    }
}

// ---------------- 2x2 mean pool (strided channel source) ---------------------
__global__ void k_pool(const float* __restrict__ in, int total, int C, int Ct, int coff,
                       int H, int W, float* __restrict__ out) {
    int idx = blockIdx.x * blockDim.x + threadIdx.x;
    if (idx >= total) return;
    int Ho = H / 2, Wo = W / 2;
    int wo = idx % Wo;
    int ho = (idx / Wo) % Ho;
    int c  = (idx / (Wo * Ho)) % C;
    int b  = idx / (Wo * Ho * C);
    const float* p = in + ((size_t)(b * Ct + coff + c) * H + 2 * ho) * W + 2 * wo;
    out[idx] = 0.25f * (p[0] + p[1] + p[W] + p[W + 1]);
}

// ---------------- bilinear 2x upsample (half-pixel) into concat dst ----------
__global__ void k_up(const float* __restrict__ in, int total, int C, int H, int W,
                     float* __restrict__ dst, int Ct, int coff) {
    int idx = blockIdx.x * blockDim.x + threadIdx.x;
    if (idx >= total) return;
    int Ho = 2 * H, Wo = 2 * W;
    int wo = idx % Wo;
    int ho = (idx / Wo) % Ho;
    int c  = (idx / (Wo * Ho)) % C;
    int b  = idx / (Wo * Ho * C);

    int kh = ho >> 1, ha, hb; float wha, whb;
    if (ho & 1) { ha = kh; hb = (kh + 1 < H) ? kh + 1 : H - 1; wha = 0.75f; whb = 0.25f; }
    else        { ha = (kh - 1 >= 0) ? kh - 1 : 0; hb = kh;    wha = 0.25f; whb = 0.75f; }
    int kw = wo >> 1, wa, wb; float wwa, wwb;
    if (wo & 1) { wa = kw; wb = (kw + 1 < W) ? kw + 1 : W - 1; wwa = 0.75f; wwb = 0.25f; }
    else        { wa = (kw - 1 >= 0) ? kw - 1 : 0; wb = kw;    wwa = 0.25f; wwb = 0.75f; }

    const float* base = in + (size_t)(b * C + c) * H * W;
    float v = wha * (wwa * base[(size_t)ha * W + wa] + wwb * base[(size_t)ha * W + wb])
            + whb * (wwa * base[(size_t)hb * W + wa] + wwb * base[(size_t)hb * W + wb]);
    dst[((size_t)(b * Ct + coff + c) * Ho + ho) * Wo + wo] = v;
}

// ------- head: fc1(64->256)+gelu+fc2(256->3), R6-proven ----------------------
__global__ void k_head(const float* __restrict__ xin, const float* __restrict__ w1,
                       const float* __restrict__ b1, const float* __restrict__ w2,
                       const float* __restrict__ b2, float* __restrict__ out) {
    __shared__ float xs[64][68];
    __shared__ float wst[64][68];   // [i][o]
    __shared__ float red[16][200];

    const int HW = 256 * 256;
    int b  = blockIdx.x >> 10;
    int p0 = (blockIdx.x & 1023) * 64;
    int tid = threadIdx.x;
    int ty = tid >> 4, tx = tid & 15;

    for (int l = tid; l < 64 * 16; l += 256) {
        int i = l >> 4, p4 = (l & 15) * 4;
        *(float4*)&xs[i][p4] =
            *(const float4*)(xin + (size_t)(b * 64 + i) * HW + p0 + p4);
    }

    float o3[3][4];
    #pragma unroll
    for (int cc = 0; cc < 3; cc++)
        #pragma unroll
        for (int c = 0; c < 4; c++) o3[cc][c] = 0.f;

    for (int oc = 0; oc < 4; oc++) {
        __syncthreads();
        for (int l = tid; l < 64 * 64; l += 256) {
            int o = l >> 6, i = l & 63;
            wst[i][o] = w1[(size_t)(oc * 64 + o) * 64 + i];
        }
        __syncthreads();

        float acc[4][4];
        #pragma unroll
        for (int r = 0; r < 4; r++) {
            float bb = b1[oc * 64 + ty * 4 + r];
            #pragma unroll
            for (int c = 0; c < 4; c++) acc[r][c] = bb;
        }
        #pragma unroll
        for (int i = 0; i < 64; i++) {
            float4 xv = *(const float4*)&xs[i][tx * 4];
            float4 wv = *(const float4*)&wst[i][ty * 4];
            acc[0][0] += wv.x * xv.x; acc[0][1] += wv.x * xv.y;
            acc[0][2] += wv.x * xv.z; acc[0][3] += wv.x * xv.w;
            acc[1][0] += wv.y * xv.x; acc[1][1] += wv.y * xv.y;
            acc[1][2] += wv.y * xv.z; acc[1][3] += wv.y * xv.w;
            acc[2][0] += wv.z * xv.x; acc[2][1] += wv.z * xv.y;
            acc[2][2] += wv.z * xv.z; acc[2][3] += wv.z * xv.w;
            acc[3][0] += wv.w * xv.x; acc[3][1] += wv.w * xv.y;
            acc[3][2] += wv.w * xv.z; acc[3][3] += wv.w * xv.w;
        }
        #pragma unroll
        for (int r = 0; r < 4; r++) {
            int o = oc * 64 + ty * 4 + r;
            float w20 = w2[o], w21 = w2[256 + o], w22 = w2[512 + o];
            #pragma unroll
            for (int c = 0; c < 4; c++) {
                float hh = gelu_f(acc[r][c]);
                o3[0][c] += hh * w20;
                o3[1][c] += hh * w21;
                o3[2][c] += hh * w22;
            }
        }
    }

    __syncthreads();
    #pragma unroll
    for (int c = 0; c < 4; c++) {
        int p = tx * 4 + c;
        red[ty][p * 3 + 0] = o3[0][c];
        red[ty][p * 3 + 1] = o3[1][c];
        red[ty][p * 3 + 2] = o3[2][c];
    }
    __syncthreads();
    if (tid < 192) {
        int p = tid / 3, cc = tid % 3;
        float s = b2[cc];
        #pragma unroll
        for (int t = 0; t < 16; t++) s += red[t][p * 3 + cc];
        out[((size_t)b * HW + p0 + p) * 3 + cc] = s;
    }
}

// =============================================================================
static inline int grid_of(int total) { return (total + 255) / 256; }

static void spectral_block(const float* xin, int Ci, int Co, int H, int m1,
                           const float* w1, const float* w2,
                           const float* cw, const float* cb,
                           const float* twW, const float* twH,
                           float* out, int Ct, int coff) {
    const int W = H, m2 = m1, m1t2 = 2 * m1;
    int BC = BSZ * Ci;
    k_fwd_w<<<BC * H / 64, 256>>>(xin, H, W, m2, twW, BC);
    k_fwd_h<<<BC * m2 / 16, 256>>>(H, BC * m2, m1, m2, twH);
    dim3 mg(BSZ * m1t2, 2);
    k_mix<<<mg, 256>>>(Ci, Co, m1, m2, w1, w2);
    k_inv_h<<<BSZ * Co, 256>>>(H, m1, m2, twH, 1.0f / (float)(H * W));
    dim3 fg(BSZ * H * W / 64, (Co + 63) / 64);
    k_fuse<<<fg, 256>>>(xin, Ci, Co, H, W, m2, twW, cw, cb, out, Ct, coff);
}

extern "C" void kernel_launch(void* const* d_in, const int* in_sizes, int n_in,
                              void* d_out, int out_size) {
    const float* x      = (const float*)d_in[0];
    const float* fcin_w = (const float*)d_in[1];
    const float* fcin_b = (const float*)d_in[2];
    const float* sc1_w1 = (const float*)d_in[3];
    const float* sc1_w2 = (const float*)d_in[4];
    const float* c1_w   = (const float*)d_in[5];
    const float* c1_b   = (const float*)d_in[6];
    const float* sc2_w1 = (const float*)d_in[7];
    const float* sc2_w2 = (const float*)d_in[8];
    const float* c2_w   = (const float*)d_in[9];
    const float* c2_b   = (const float*)d_in[10];
    const float* scb_w1 = (const float*)d_in[11];
    const float* scb_w2 = (const float*)d_in[12];
    const float* cb_w   = (const float*)d_in[13];
    const float* cb_b   = (const float*)d_in[14];
    const float* su2_w1 = (const float*)d_in[15];
    const float* su2_w2 = (const float*)d_in[16];
    const float* u2_w   = (const float*)d_in[17];
    const float* u2_b   = (const float*)d_in[18];
    const float* su1_w1 = (const float*)d_in[19];
    const float* su1_w2 = (const float*)d_in[20];
    const float* u1_w   = (const float*)d_in[21];
    const float* u1_b   = (const float*)d_in[22];
    const float* fc1_w  = (const float*)d_in[23];
    const float* fc1_b  = (const float*)d_in[24];
    const float* fc2_w  = (const float*)d_in[25];
    const float* fc2_b  = (const float*)d_in[26];

    float *p_v, *p_x1d, *p_x2d, *p_xb, *p_x2c, *p_x2o, *p_x1c, *p_x1o, *p_tw;
    cudaGetSymbolAddress((void**)&p_v,   g_v);
    cudaGetSymbolAddress((void**)&p_x1d, g_x1d);
    cudaGetSymbolAddress((void**)&p_x2d, g_x2d);
    cudaGetSymbolAddress((void**)&p_xb,  g_xb);
    cudaGetSymbolAddress((void**)&p_x2c, g_x2c);
    cudaGetSymbolAddress((void**)&p_x2o, g_x2o);
    cudaGetSymbolAddress((void**)&p_x1c, g_x1c);
    cudaGetSymbolAddress((void**)&p_x1o, g_x1o);
    cudaGetSymbolAddress((void**)&p_tw,  g_tw);

    const float* tw_W0 = p_tw + 2 * TW0;
    const float* tw_H0 = p_tw + 2 * TH0;
    const float* tw_W1 = p_tw + 2 * TW1;
    const float* tw_H1 = p_tw + 2 * TH1;
    const float* tw_W2 = p_tw + 2 * TW2;
    const float* tw_H2 = p_tw + 2 * TH2;

    k_init_tw<<<32, 256>>>();

    // lift 6 -> 64
    {
        int t = BSZ * 64 * 256 * 256;
        k_lift<<<grid_of(t), 256>>>(x, fcin_w, fcin_b);
    }

    // encoder level 1: 64 -> 64 @ 256 ; x1 written directly into x1c[96:160]
    spectral_block(p_v, 64, 64, 256, 12, sc1_w1, sc1_w2, c1_w, c1_b, tw_W0, tw_H0,
                   p_x1c, 160, 96);
    {
        int t = BSZ * 64 * 128 * 128;
        k_pool<<<grid_of(t), 256>>>(p_x1c, t, 64, 160, 96, 256, 256, p_x1d);
    }

    // encoder level 2: 64 -> 96 @ 128 ; x2 written into x2c[128:224]
    spectral_block(p_x1d, 64, 96, 128, 8, sc2_w1, sc2_w2, c2_w, c2_b, tw_W1, tw_H1,
                   p_x2c, 224, 128);
    {
        int t = BSZ * 96 * 64 * 64;
        k_pool<<<grid_of(t), 256>>>(p_x2c, t, 96, 224, 128, 128, 128, p_x2d);
    }

    // bottleneck: 96 -> 128 @ 64
    spectral_block(p_x2d, 96, 128, 64, 4, scb_w1, scb_w2, cb_w, cb_b, tw_W2, tw_H2,
                   p_xb, 128, 0);

    // up(xb) -> x2c[0:128]
    {
        int t = BSZ * 128 * 128 * 128;
        k_up<<<grid_of(t), 256>>>(p_xb, t, 128, 64, 64, p_x2c, 224, 0);
    }

    // decoder level 2: 224 -> 96 @ 128
    spectral_block(p_x2c, 224, 96, 128, 8, su2_w1, su2_w2, u2_w, u2_b, tw_W1, tw_H1,
                   p_x2o, 96, 0);

    // up(x2o) -> x1c[0:96]
    {
        int t = BSZ * 96 * 256 * 256;
        k_up<<<grid_of(t), 256>>>(p_x2o, t, 96, 128, 128, p_x1c, 160, 0);
    }

    // decoder level 1: 160 -> 64 @ 256
    spectral_block(p_x1c, 160, 64, 256, 12, su1_w1, su1_w2, u1_w, u1_b, tw_W0, tw_H0,
                   p_x1o, 64, 0);

    // head: fc1 + gelu + fc2 fused
    k_head<<<BSZ * 1024, 256>>>(p_x1o, fc1_w, fc1_b, fc2_w, fc2_b, (float*)d_out);
}

// round 9
// speedup vs baseline: 1.1646x; 1.0435x over previous
#include <cuda_runtime.h>
#include <math.h>

#define BSZ 4

// ---------------- scratch (device globals; no allocations allowed) ----------
__device__ float g_v  [16777216];   // [4,64,256,256]
__device__ float g_x1d[ 4194304];   // [4,64,128,128]
__device__ float g_x2d[ 1572864];   // [4,96,64,64]
__device__ float g_xb [ 2097152];   // [4,128,64,64]
__device__ float g_x2c[14680064];   // [4,224,128,128] (x2 at coff 128)
__device__ float g_x2o[ 6291456];   // [4,96,128,128]
__device__ float g_x1c[41943040];   // [4,160,256,256] (x1 at coff 96)
__device__ float g_x1o[16777216];   // [4,64,256,256]

__device__ float g_XW [ 3932160];   // transposed: [H][BC*m2c]
__device__ float g_XF [  368640];   // [BC,2m1,m2] complex
__device__ float g_OF [  368640];   // [B,Co,2m1,m2] complex
__device__ float g_Z  [ 1572864];   // [B,Co,H,m2] complex (scaled)
__device__ float g_tw [   26112];   // twiddle tables (complex interleaved)

#define TW0 0
#define TH0 3072
#define TW1 9216
#define TH1 10240
#define TW2 12288
#define TH2 12544

__device__ __forceinline__ float gelu_f(float x) {
    return 0.5f * x * (1.0f + erff(x * 0.70710678118654752f));
}

// ---------------- twiddle init -----------------------------------------------
__global__ void k_init_tw() {
    const int cfg[3][5] = {{256,12,12,TW0,TH0},{128,8,8,TW1,TH1},{64,4,4,TW2,TH2}};
    int tid = blockIdx.x * blockDim.x + threadIdx.x;
    int nth = gridDim.x * blockDim.x;
    for (int c = 0; c < 3; c++) {
        int H = cfg[c][0], m1 = cfg[c][1], m2 = cfg[c][2];
        int offW = cfg[c][3], offH = cfg[c][4];
        int nW = H * m2;
        for (int e = tid; e < nW; e += nth) {
            int w = e / m2, kw = e % m2;
            int p = (w * kw) % H;
            double s, co; sincos(2.0 * 3.14159265358979323846 * (double)p / (double)H, &s, &co);
            g_tw[(offW + e) * 2]     = (float)co;
            g_tw[(offW + e) * 2 + 1] = (float)(-s);
        }
        int m1t2 = 2 * m1;
        int nH = H * m1t2;
        for (int e = tid; e < nH; e += nth) {
            int h = e / m1t2, j = e % m1t2;
            int kh = (j < m1) ? j : (H - 2 * m1 + j);
            int p = (kh * h) % H;
            double s, co; sincos(2.0 * 3.14159265358979323846 * (double)p / (double)H, &s, &co);
            g_tw[(offH + e) * 2]     = (float)co;
            g_tw[(offH + e) * 2 + 1] = (float)(-s);
        }
    }
}

// ---------------- lift: x[B,H,W,6] -> v[B,64,H,W] ----------------------------
__global__ void k_lift(const float* __restrict__ x, const float* __restrict__ w,
                       const float* __restrict__ b) {
    const int HW = 256 * 256;
    int idx = blockIdx.x * blockDim.x + threadIdx.x;
    if (idx >= BSZ * 64 * HW) return;
    int p  = idx % HW;
    int c  = (idx / HW) % 64;
    int bb = idx / (HW * 64);
    const float* xp = x + ((size_t)bb * HW + p) * 6;
    float acc = b[c];
    #pragma unroll
    for (int i = 0; i < 6; i++) acc += xp[i] * w[c * 6 + i];
    g_v[idx] = acc;
}

// ------- fwd DFT along W: x rows -> XWt[h][bc*m2c] (transposed) -------------
__global__ void k_fwd_w(const float* __restrict__ xin, int H, int W, int m2,
                        const float* __restrict__ tw, int BC) {
    __shared__ float xs[64][68];
    __shared__ float tws[64][24];
    int m2c = 2 * m2;
    int r0 = blockIdx.x * 64;
    int tid = threadIdx.x;
    int row_l = tid & 31;
    int kc0 = tid >> 5;
    bool v1 = (kc0 + 8 < m2c), v2 = (kc0 + 16 < m2c);
    float a00 = 0.f, a01 = 0.f, a02 = 0.f, a10 = 0.f, a11 = 0.f, a12 = 0.f;

    for (int k0 = 0; k0 < W; k0 += 64) {
        for (int l = tid; l < 64 * 16; l += 256) {
            int r = l >> 4, k4 = (l & 15) * 4;
            float4 v = *(const float4*)(xin + (size_t)(r0 + r) * W + k0 + k4);
            *(float4*)&xs[r][k4] = v;
        }
        for (int l = tid; l < 64 * m2c; l += 256) {
            int k = l / m2c, kc = l % m2c;
            tws[k][kc] = tw[(size_t)(k0 + k) * m2c + kc];
        }
        __syncthreads();
        #pragma unroll 4
        for (int k = 0; k < 64; k++) {
            float x0 = xs[row_l][k];
            float x1 = xs[row_l + 32][k];
            float t0 = tws[k][kc0];
            a00 += x0 * t0; a10 += x1 * t0;
            if (v1) { float t1 = tws[k][kc0 + 8];  a01 += x0 * t1; a11 += x1 * t1; }
            if (v2) { float t2 = tws[k][kc0 + 16]; a02 += x0 * t2; a12 += x1 * t2; }
        }
        __syncthreads();
    }
    int r = r0 + row_l;
    int bc = r / H, h = r - bc * H;
    size_t base = ((size_t)h * BC + bc) * m2c;
    g_XW[base + kc0] = a00;
    if (v1) g_XW[base + kc0 + 8]  = a01;
    if (v2) g_XW[base + kc0 + 16] = a02;
    r = r0 + row_l + 32;
    bc = r / H; h = r - bc * H;
    base = ((size_t)h * BC + bc) * m2c;
    g_XW[base + kc0] = a10;
    if (v1) g_XW[base + kc0 + 8]  = a11;
    if (v2) g_XW[base + kc0 + 16] = a12;
}

// ------- fwd DFT along H: 256 threads, 16 complex cols per block -------------
__global__ void k_fwd_h(int H, int BCm2, int m1, int m2, const float* __restrict__ tw) {
    __shared__ float xs[64][32];
    __shared__ float tws[64][48];
    int m1t2 = 2 * m1;
    int cc0 = blockIdx.x * 16;
    int tid = threadIdx.x;
    int cl = tid & 15;
    int g  = tid >> 4;          // 0..15
    bool v0 = (g < m1t2);
    bool v1 = (g + 16 < m1t2);
    float ar0 = 0.f, ai0 = 0.f, ar1 = 0.f, ai1 = 0.f;
    int N2 = BCm2 * 2;

    for (int h0 = 0; h0 < H; h0 += 64) {
        for (int l = tid; l < 64 * 8; l += 256) {
            int hh = l >> 3, c4 = (l & 7) * 4;
            *(float4*)&xs[hh][c4] =
                *(const float4*)(g_XW + (size_t)(h0 + hh) * N2 + cc0 * 2 + c4);
        }
        for (int l = tid; l < 64 * m1t2 * 2; l += 256) {
            int hh = l / (m1t2 * 2), c = l % (m1t2 * 2);
            tws[hh][c] = tw[(size_t)(h0 + hh) * m1t2 * 2 + c];
        }
        __syncthreads();
        #pragma unroll 4
        for (int hh = 0; hh < 64; hh++) {
            float2 xv = *(const float2*)&xs[hh][2 * cl];
            if (v0) {
                float tr = tws[hh][2 * g], ti = tws[hh][2 * g + 1];
                ar0 += xv.x * tr - xv.y * ti;
                ai0 += xv.x * ti + xv.y * tr;
            }
            if (v1) {
                float tr1 = tws[hh][2 * (g + 16)], ti1 = tws[hh][2 * (g + 16) + 1];
                ar1 += xv.x * tr1 - xv.y * ti1;
                ai1 += xv.x * ti1 + xv.y * tr1;
            }
        }
        __syncthreads();
    }
    int cc = cc0 + cl, bc = cc / m2, kw = cc % m2;
    if (v0) {
        size_t oo = (((size_t)bc * m1t2 + g) * m2 + kw) * 2;
        g_XF[oo] = ar0; g_XF[oo + 1] = ai0;
    }
    if (v1) {
        size_t oo = (((size_t)bc * m1t2 + g + 16) * m2 + kw) * 2;
        g_XF[oo] = ar1; g_XF[oo + 1] = ai1;
    }
}

// ------- per-mode channel mix; Co split over blockIdx.y -----------------------
__global__ void k_mix(int Ci, int Co, int m1, int m2,
                      const float* __restrict__ w1, const float* __restrict__ w2) {
    __shared__ float xf_s[3840];
    int m1t2 = 2 * m1, m2c = 2 * m2;
    int kk = blockIdx.x % m1t2;
    int b  = blockIdx.x / m1t2;
    int oy = blockIdx.y;
    int tid = threadIdx.x;

    for (int l = tid; l < Ci * m2c; l += 256) {
        int i = l / m2c, kc = l % m2c;
        xf_s[l] = g_XF[(((size_t)(b * Ci + i) * m1t2 + kk) * m2) * 2 + kc];
    }
    __syncthreads();

    int kkr = (kk < m1) ? kk : kk - m1;
    const float* wsel = (kk < m1) ? w1 : w2;
    int wstride = Co * m1 * m2 * 2;
    int nout = Co * m2;
    int half = nout >> 1;
    int e_begin = oy * half;
    int e_end   = e_begin + half;
    for (int e0 = e_begin + tid; e0 < e_end; e0 += 1024) {
        float orr[4] = {0,0,0,0}, oii[4] = {0,0,0,0};
        int xoff[4], woff[4]; bool val[4];
        #pragma unroll
        for (int u = 0; u < 4; u++) {
            int e = e0 + 256 * u;
            val[u] = (e < e_end);
            int kw = val[u] ? e % m2 : 0;
            int o  = val[u] ? e / m2 : 0;
            xoff[u] = 2 * kw;
            woff[u] = ((o * m1 + kkr) * m2 + kw) * 2;
        }
        for (int i = 0; i < Ci; i++) {
            const float* wrow = wsel + (size_t)i * wstride;
            const float* xrow = xf_s + i * m2c;
            #pragma unroll
            for (int u = 0; u < 4; u++) {
                float xr = xrow[xoff[u]], xi = xrow[xoff[u] + 1];
                float wr = wrow[woff[u]], wi = wrow[woff[u] + 1];
                orr[u] += xr * wr - xi * wi;
                oii[u] += xr * wi + xi * wr;
            }
        }
        #pragma unroll
        for (int u = 0; u < 4; u++) {
            if (val[u]) {
                int e = e0 + 256 * u;
                int kw = e % m2, o = e / m2;
                size_t oo = (((size_t)(b * Co + o) * m1t2 + kk) * m2 + kw) * 2;
                g_OF[oo] = orr[u]; g_OF[oo + 1] = oii[u];
            }
        }
    }
}

// ------- inverse DFT along H ---------------------------------------------------
__global__ void k_inv_h(int H, int m1, int m2, const float* __restrict__ tw,
                        float invHW) {
    __shared__ float of_s[1152];
    int bo = blockIdx.x;
    int tid = threadIdx.x;
    int m1t2 = 2 * m1;
    int nload = m1t2 * m2 * 2;
    const float* src = g_OF + (size_t)bo * nload;
    for (int l = tid; l < nload; l += 256) of_s[l] = src[l];
    __syncthreads();

    int nout = H * m2;
    for (int e = tid; e < nout; e += 512) {
        int e2 = e + 256;
        bool v2 = (e2 < nout);
        int kw0 = e % m2, h0 = e / m2;
        int kw1 = v2 ? e2 % m2 : 0, h1 = v2 ? e2 / m2 : 0;
        float zr0 = 0.f, zi0 = 0.f, zr1 = 0.f, zi1 = 0.f;
        for (int kk = 0; kk < m1t2; kk++) {
            float tr0 = tw[(h0 * m1t2 + kk) * 2], ti0 = tw[(h0 * m1t2 + kk) * 2 + 1];
            float fr0 = of_s[(kk * m2 + kw0) * 2], fi0 = of_s[(kk * m2 + kw0) * 2 + 1];
            zr0 += fr0 * tr0 + fi0 * ti0;
            zi0 += fi0 * tr0 - fr0 * ti0;
            float tr1 = tw[(h1 * m1t2 + kk) * 2], ti1 = tw[(h1 * m1t2 + kk) * 2 + 1];
            float fr1 = of_s[(kk * m2 + kw1) * 2], fi1 = of_s[(kk * m2 + kw1) * 2 + 1];
            zr1 += fr1 * tr1 + fi1 * ti1;
            zi1 += fi1 * tr1 - fr1 * ti1;
        }
        size_t oo = ((size_t)bo * nout + e) * 2;
        g_Z[oo] = zr0 * invHW; g_Z[oo + 1] = zi0 * invHW;
        if (v2) {
            oo = ((size_t)bo * nout + e2) * 2;
            g_Z[oo] = zr1 * invHW; g_Z[oo + 1] = zi1 * invHW;
        }
    }
}

// ------- fused GEMM: out = gelu(conv1x1 + bias + invW(Z)) --------------------
// 64ch x 64px, 4x4 microtile, K-chunk 32; spec as priming GEMM (K=2m2);
// register-prefetch double buffering of x/w chunks.
__global__ void k_fuse(const float* __restrict__ xin, int Ci, int Co,
                       int H, int W, int m2, const float* __restrict__ tw,
                       const float* __restrict__ cw, const float* __restrict__ cb,
                       float* __restrict__ out, int Ct, int coff) {
    __shared__ float xs[32][68];
    __shared__ float wst[32][68];   // [i][o]
    __shared__ float zst[24][68];   // [r][o]
    __shared__ float twst[24][68];  // [r][p]

    const int HW = H * W;
    int tilesPerImg = HW >> 6;
    int b  = blockIdx.x / tilesPerImg;
    int p0 = (blockIdx.x % tilesPerImg) << 6;
    int ob = blockIdx.y << 6;
    int h  = p0 / W, w0 = p0 % W;
    int tid = threadIdx.x;
    int ty = tid >> 4, tx = tid & 15;
    int m2c = 2 * m2;

    // stage spectral operands transposed
    for (int l = tid; l < m2c * 64; l += 256) {
        int r = l >> 6, o = l & 63;
        int oo = ob + o;
        float v = (oo < Co) ? g_Z[(((size_t)(b * Co + oo) * H + h) * m2) * 2 + r] : 0.f;
        zst[r][o] = (r >= 2) ? 2.0f * v : v;
    }
    for (int l = tid; l < m2c * 64; l += 256) {
        int r = l >> 6, p = l & 63;
        twst[r][p] = tw[(size_t)(w0 + p) * m2c + r];
    }

    // prefetch chunk 0 (x: 2 float4; w: 2 float4 rows)
    float4 xpre0, xpre1, wpre0, wpre1;
    {
        int l0 = tid, l1 = tid + 256;
        int i0 = l0 >> 4, q0 = (l0 & 15) * 4;
        int i1 = l1 >> 4, q1 = (l1 & 15) * 4;
        xpre0 = *(const float4*)(xin + (size_t)(b * Ci + i0) * HW + p0 + q0);
        xpre1 = *(const float4*)(xin + (size_t)(b * Ci + i1) * HW + p0 + q1);
        int o0 = l0 >> 3, j0 = (l0 & 7) * 4;
        int o1 = l1 >> 3, j1 = (l1 & 7) * 4;
        int oo0 = ob + o0, oo1 = ob + o1;
        wpre0 = (oo0 < Co) ? *(const float4*)(cw + (size_t)oo0 * Ci + j0)
                           : make_float4(0.f, 0.f, 0.f, 0.f);
        wpre1 = (oo1 < Co) ? *(const float4*)(cw + (size_t)oo1 * Ci + j1)
                           : make_float4(0.f, 0.f, 0.f, 0.f);
    }
    __syncthreads();

    // prime acc with spectral GEMM (K = m2c)
    float acc[4][4];
    #pragma unroll
    for (int r = 0; r < 4; r++)
        #pragma unroll
        for (int c = 0; c < 4; c++) acc[r][c] = 0.f;
    for (int r = 0; r < m2c; r++) {
        float4 zv = *(const float4*)&zst[r][ty * 4];
        float4 tv = *(const float4*)&twst[r][tx * 4];
        acc[0][0] += zv.x * tv.x; acc[0][1] += zv.x * tv.y;
        acc[0][2] += zv.x * tv.z; acc[0][3] += zv.x * tv.w;
        acc[1][0] += zv.y * tv.x; acc[1][1] += zv.y * tv.y;
        acc[1][2] += zv.y * tv.z; acc[1][3] += zv.y * tv.w;
        acc[2][0] += zv.z * tv.x; acc[2][1] += zv.z * tv.y;
        acc[2][2] += zv.z * tv.z; acc[2][3] += zv.z * tv.w;
        acc[3][0] += zv.w * tv.x; acc[3][1] += zv.w * tv.y;
        acc[3][2] += zv.w * tv.z; acc[3][3] += zv.w * tv.w;
    }

    // conv1x1 main loop with register-prefetch double buffering
    for (int ci0 = 0; ci0 < Ci; ci0 += 32) {
        __syncthreads();
        // store prefetched chunk to smem
        {
            int l0 = tid, l1 = tid + 256;
            int i0 = l0 >> 4, q0 = (l0 & 15) * 4;
            int i1 = l1 >> 4, q1 = (l1 & 15) * 4;
            *(float4*)&xs[i0][q0] = xpre0;
            *(float4*)&xs[i1][q1] = xpre1;
            int o0 = l0 >> 3, j0 = (l0 & 7) * 4;
            int o1 = l1 >> 3, j1 = (l1 & 7) * 4;
            wst[j0][o0] = wpre0.x; wst[j0 + 1][o0] = wpre0.y;
            wst[j0 + 2][o0] = wpre0.z; wst[j0 + 3][o0] = wpre0.w;
            wst[j1][o1] = wpre1.x; wst[j1 + 1][o1] = wpre1.y;
            wst[j1 + 2][o1] = wpre1.z; wst[j1 + 3][o1] = wpre1.w;
        }
        __syncthreads();
        // prefetch next chunk (overlaps compute below)
        int cin = ci0 + 32;
        if (cin < Ci) {
            int l0 = tid, l1 = tid + 256;
            int i0 = l0 >> 4, q0 = (l0 & 15) * 4;
            int i1 = l1 >> 4, q1 = (l1 & 15) * 4;
            xpre0 = *(const float4*)(xin + (size_t)(b * Ci + cin + i0) * HW + p0 + q0);
            xpre1 = *(const float4*)(xin + (size_t)(b * Ci + cin + i1) * HW + p0 + q1);
            int o0 = l0 >> 3, j0 = (l0 & 7) * 4;
            int o1 = l1 >> 3, j1 = (l1 & 7) * 4;
            int oo0 = ob + o0, oo1 = ob + o1;
            wpre0 = (oo0 < Co) ? *(const float4*)(cw + (size_t)oo0 * Ci + cin + j0)
                               : make_float4(0.f, 0.f, 0.f, 0.f);
            wpre1 = (oo1 < Co) ? *(const float4*)(cw + (size_t)oo1 * Ci + cin + j1)
                               : make_float4(0.f, 0.f, 0.f, 0.f);
        }
        #pragma unroll
        for (int i = 0; i < 32; i++) {
            float4 xv = *(const float4*)&xs[i][tx * 4];
            float4 wv = *(const float4*)&wst[i][ty * 4];
            acc[0][0] += wv.x * xv.x; acc[0][1] += wv.x * xv.y;
            acc[0][2] += wv.x * xv.z; acc[0][3] += wv.x * xv.w;
            acc[1][0] += wv.y * xv.x; acc[1][1] += wv.y * xv.y;
            acc[1][2] += wv.y * xv.z; acc[1][3] += wv.y * xv.w;
            acc[2][0] += wv.z * xv.x; acc[2][1] += wv.z * xv.y;
            acc[2][2] += wv.z * xv.z; acc[2][3] += wv.z * xv.w;
            acc[3][0] += wv.w * xv.x; acc[3][1] += wv.w * xv.y;
            acc[3][2] += wv.w * xv.z; acc[3][3] += wv.w * xv.w;
        }
    }

    #pragma unroll
    for (int r = 0; r < 4; r++) {
        int oo = ob + ty * 4 + r;
        if (oo >= Co) continue;
        float bias = cb[oo];
        float res[4];
        #pragma unroll
        for (int c = 0; c < 4; c++) res[c] = gelu_f(acc[r][c] + bias);
        *(float4*)(out + (size_t)(b * Ct + coff + oo) * HW + p0 + tx * 4) =
            make_float4(res[0], res[1], res[2], res[3]);
    }
}

// ---------------- 2x2 mean pool (strided channel source) ---------------------
__global__ void k_pool(const float* __restrict__ in, int total, int C, int Ct, int coff,
                       int H, int W, float* __restrict__ out) {
    int idx = blockIdx.x * blockDim.x + threadIdx.x;
    if (idx >= total) return;
    int Ho = H / 2, Wo = W / 2;
    int wo = idx % Wo;
    int ho = (idx / Wo) % Ho;
    int c  = (idx / (Wo * Ho)) % C;
    int b  = idx / (Wo * Ho * C);
    const float* p = in + ((size_t)(b * Ct + coff + c) * H + 2 * ho) * W + 2 * wo;
    out[idx] = 0.25f * (p[0] + p[1] + p[W] + p[W + 1]);
}

// ---------------- bilinear 2x upsample (half-pixel) into concat dst ----------
__global__ void k_up(const float* __restrict__ in, int total, int C, int H, int W,
                     float* __restrict__ dst, int Ct, int coff) {
    int idx = blockIdx.x * blockDim.x + threadIdx.x;
    if (idx >= total) return;
    int Ho = 2 * H, Wo = 2 * W;
    int wo = idx % Wo;
    int ho = (idx / Wo) % Ho;
    int c  = (idx / (Wo * Ho)) % C;
    int b  = idx / (Wo * Ho * C);

    int kh = ho >> 1, ha, hb; float wha, whb;
    if (ho & 1) { ha = kh; hb = (kh + 1 < H) ? kh + 1 : H - 1; wha = 0.75f; whb = 0.25f; }
    else        { ha = (kh - 1 >= 0) ? kh - 1 : 0; hb = kh;    wha = 0.25f; whb = 0.75f; }
    int kw = wo >> 1, wa, wb; float wwa, wwb;
    if (wo & 1) { wa = kw; wb = (kw + 1 < W) ? kw + 1 : W - 1; wwa = 0.75f; wwb = 0.25f; }
    else        { wa = (kw - 1 >= 0) ? kw - 1 : 0; wb = kw;    wwa = 0.25f; wwb = 0.75f; }

    const float* base = in + (size_t)(b * C + c) * H * W;
    float v = wha * (wwa * base[(size_t)ha * W + wa] + wwb * base[(size_t)ha * W + wb])
            + whb * (wwa * base[(size_t)hb * W + wa] + wwb * base[(size_t)hb * W + wb]);
    dst[((size_t)(b * Ct + coff + c) * Ho + ho) * Wo + wo] = v;
}

// ------- head: fc1(64->256)+gelu+fc2(256->3); w1 register-prefetch -----------
__global__ void k_head(const float* __restrict__ xin, const float* __restrict__ w1,
                       const float* __restrict__ b1, const float* __restrict__ w2,
                       const float* __restrict__ b2, float* __restrict__ out) {
    __shared__ float xs[64][68];
    __shared__ float wst[64][68];   // [i][o]
    __shared__ float red[16][200];

    const int HW = 256 * 256;
    int b  = blockIdx.x >> 10;
    int p0 = (blockIdx.x & 1023) * 64;
    int tid = threadIdx.x;
    int ty = tid >> 4, tx = tid & 15;

    for (int l = tid; l < 64 * 16; l += 256) {
        int i = l >> 4, p4 = (l & 15) * 4;
        *(float4*)&xs[i][p4] =
            *(const float4*)(xin + (size_t)(b * 64 + i) * HW + p0 + p4);
    }

    // prefetch w1 chunk for oc=0: 1024 float4 loads over 256 threads = 4/thread
    float4 wpre[4];
    #pragma unroll
    for (int u = 0; u < 4; u++) {
        int l = tid + 256 * u;
        int o = l >> 4, j = (l & 15) * 4;
        wpre[u] = *(const float4*)(w1 + (size_t)o * 64 + j);
    }

    float o3[3][4];
    #pragma unroll
    for (int cc = 0; cc < 3; cc++)
        #pragma unroll
        for (int c = 0; c < 4; c++) o3[cc][c] = 0.f;

    for (int oc = 0; oc < 4; oc++) {
        __syncthreads();
        #pragma unroll
        for (int u = 0; u < 4; u++) {
            int l = tid + 256 * u;
            int o = l >> 4, j = (l & 15) * 4;
            wst[j][o] = wpre[u].x; wst[j + 1][o] = wpre[u].y;
            wst[j + 2][o] = wpre[u].z; wst[j + 3][o] = wpre[u].w;
        }
        __syncthreads();
        if (oc < 3) {
            #pragma unroll
            for (int u = 0; u < 4; u++) {
                int l = tid + 256 * u;
                int o = l >> 4, j = (l & 15) * 4;
                wpre[u] = *(const float4*)(w1 + (size_t)((oc + 1) * 64 + o) * 64 + j);
            }
        }

        float acc[4][4];
        #pragma unroll
        for (int r = 0; r < 4; r++) {
            float bb = b1[oc * 64 + ty * 4 + r];
            #pragma unroll
            for (int c = 0; c < 4; c++) acc[r][c] = bb;
        }
        #pragma unroll
        for (int i = 0; i < 64; i++) {
            float4 xv = *(const float4*)&xs[i][tx * 4];
            float4 wv = *(const float4*)&wst[i][ty * 4];
            acc[0][0] += wv.x * xv.x; acc[0][1] += wv.x * xv.y;
            acc[0][2] += wv.x * xv.z; acc[0][3] += wv.x * xv.w;
            acc[1][0] += wv.y * xv.x; acc[1][1] += wv.y * xv.y;
            acc[1][2] += wv.y * xv.z; acc[1][3] += wv.y * xv.w;
            acc[2][0] += wv.z * xv.x; acc[2][1] += wv.z * xv.y;
            acc[2][2] += wv.z * xv.z; acc[2][3] += wv.z * xv.w;
            acc[3][0] += wv.w * xv.x; acc[3][1] += wv.w * xv.y;
            acc[3][2] += wv.w * xv.z; acc[3][3] += wv.w * xv.w;
        }
        #pragma unroll
        for (int r = 0; r < 4; r++) {
            int o = oc * 64 + ty * 4 + r;
            float w20 = w2[o], w21 = w2[256 + o], w22 = w2[512 + o];
            #pragma unroll
            for (int c = 0; c < 4; c++) {
                float hh = gelu_f(acc[r][c]);
                o3[0][c] += hh * w20;
                o3[1][c] += hh * w21;
                o3[2][c] += hh * w22;
            }
        }
    }

    __syncthreads();
    #pragma unroll
    for (int c = 0; c < 4; c++) {
        int p = tx * 4 + c;
        red[ty][p * 3 + 0] = o3[0][c];
        red[ty][p * 3 + 1] = o3[1][c];
        red[ty][p * 3 + 2] = o3[2][c];
    }
    __syncthreads();
    if (tid < 192) {
        int p = tid / 3, cc = tid % 3;
        float s = b2[cc];
        #pragma unroll
        for (int t = 0; t < 16; t++) s += red[t][p * 3 + cc];
        out[((size_t)b * HW + p0 + p) * 3 + cc] = s;
    }
}

// =============================================================================
static inline int grid_of(int total) { return (total + 255) / 256; }

static void spectral_block(const float* xin, int Ci, int Co, int H, int m1,
                           const float* w1, const float* w2,
                           const float* cw, const float* cb,
                           const float* twW, const float* twH,
                           float* out, int Ct, int coff) {
    const int W = H, m2 = m1, m1t2 = 2 * m1;
    int BC = BSZ * Ci;
    k_fwd_w<<<BC * H / 64, 256>>>(xin, H, W, m2, twW, BC);
    k_fwd_h<<<BC * m2 / 16, 256>>>(H, BC * m2, m1, m2, twH);
    dim3 mg(BSZ * m1t2, 2);
    k_mix<<<mg, 256>>>(Ci, Co, m1, m2, w1, w2);
    k_inv_h<<<BSZ * Co, 256>>>(H, m1, m2, twH, 1.0f / (float)(H * W));
    dim3 fg(BSZ * H * W / 64, (Co + 63) / 64);
    k_fuse<<<fg, 256>>>(xin, Ci, Co, H, W, m2, twW, cw, cb, out, Ct, coff);
}

extern "C" void kernel_launch(void* const* d_in, const int* in_sizes, int n_in,
                              void* d_out, int out_size) {
    const float* x      = (const float*)d_in[0];
    const float* fcin_w = (const float*)d_in[1];
    const float* fcin_b = (const float*)d_in[2];
    const float* sc1_w1 = (const float*)d_in[3];
    const float* sc1_w2 = (const float*)d_in[4];
    const float* c1_w   = (const float*)d_in[5];
    const float* c1_b   = (const float*)d_in[6];
    const float* sc2_w1 = (const float*)d_in[7];
    const float* sc2_w2 = (const float*)d_in[8];
    const float* c2_w   = (const float*)d_in[9];
    const float* c2_b   = (const float*)d_in[10];
    const float* scb_w1 = (const float*)d_in[11];
    const float* scb_w2 = (const float*)d_in[12];
    const float* cb_w   = (const float*)d_in[13];
    const float* cb_b   = (const float*)d_in[14];
    const float* su2_w1 = (const float*)d_in[15];
    const float* su2_w2 = (const float*)d_in[16];
    const float* u2_w   = (const float*)d_in[17];
    const float* u2_b   = (const float*)d_in[18];
    const float* su1_w1 = (const float*)d_in[19];
    const float* su1_w2 = (const float*)d_in[20];
    const float* u1_w   = (const float*)d_in[21];
    const float* u1_b   = (const float*)d_in[22];
    const float* fc1_w  = (const float*)d_in[23];
    const float* fc1_b  = (const float*)d_in[24];
    const float* fc2_w  = (const float*)d_in[25];
    const float* fc2_b  = (const float*)d_in[26];

    float *p_v, *p_x1d, *p_x2d, *p_xb, *p_x2c, *p_x2o, *p_x1c, *p_x1o, *p_tw;
    cudaGetSymbolAddress((void**)&p_v,   g_v);
    cudaGetSymbolAddress((void**)&p_x1d, g_x1d);
    cudaGetSymbolAddress((void**)&p_x2d, g_x2d);
    cudaGetSymbolAddress((void**)&p_xb,  g_xb);
    cudaGetSymbolAddress((void**)&p_x2c, g_x2c);
    cudaGetSymbolAddress((void**)&p_x2o, g_x2o);
    cudaGetSymbolAddress((void**)&p_x1c, g_x1c);
    cudaGetSymbolAddress((void**)&p_x1o, g_x1o);
    cudaGetSymbolAddress((void**)&p_tw,  g_tw);

    const float* tw_W0 = p_tw + 2 * TW0;
    const float* tw_H0 = p_tw + 2 * TH0;
    const float* tw_W1 = p_tw + 2 * TW1;
    const float* tw_H1 = p_tw + 2 * TH1;
    const float* tw_W2 = p_tw + 2 * TW2;
    const float* tw_H2 = p_tw + 2 * TH2;

    k_init_tw<<<32, 256>>>();

    // lift 6 -> 64
    {
        int t = BSZ * 64 * 256 * 256;
        k_lift<<<grid_of(t), 256>>>(x, fcin_w, fcin_b);
    }

    // encoder level 1: 64 -> 64 @ 256 ; x1 written directly into x1c[96:160]
    spectral_block(p_v, 64, 64, 256, 12, sc1_w1, sc1_w2, c1_w, c1_b, tw_W0, tw_H0,
                   p_x1c, 160, 96);
    {
        int t = BSZ * 64 * 128 * 128;
        k_pool<<<grid_of(t), 256>>>(p_x1c, t, 64, 160, 96, 256, 256, p_x1d);
    }

    // encoder level 2: 64 -> 96 @ 128 ; x2 written into x2c[128:224]
    spectral_block(p_x1d, 64, 96, 128, 8, sc2_w1, sc2_w2, c2_w, c2_b, tw_W1, tw_H1,
                   p_x2c, 224, 128);
    {
        int t = BSZ * 96 * 64 * 64;
        k_pool<<<grid_of(t), 256>>>(p_x2c, t, 96, 224, 128, 128, 128, p_x2d);
    }

    // bottleneck: 96 -> 128 @ 64
    spectral_block(p_x2d, 96, 128, 64, 4, scb_w1, scb_w2, cb_w, cb_b, tw_W2, tw_H2,
                   p_xb, 128, 0);

    // up(xb) -> x2c[0:128]
    {
        int t = BSZ * 128 * 128 * 128;
        k_up<<<grid_of(t), 256>>>(p_xb, t, 128, 64, 64, p_x2c, 224, 0);
    }

    // decoder level 2: 224 -> 96 @ 128
    spectral_block(p_x2c, 224, 96, 128, 8, su2_w1, su2_w2, u2_w, u2_b, tw_W1, tw_H1,
                   p_x2o, 96, 0);

    // up(x2o) -> x1c[0:96]
    {
        int t = BSZ * 96 * 256 * 256;
        k_up<<<grid_of(t), 256>>>(p_x2o, t, 96, 128, 128, p_x1c, 160, 0);
    }

    // decoder level 1: 160 -> 64 @ 256
    spectral_block(p_x1c, 160, 64, 256, 12, su1_w1, su1_w2, u1_w, u1_b, tw_W0, tw_H0,
                   p_x1o, 64, 0);

    // head: fc1 + gelu + fc2 fused
    k_head<<<BSZ * 1024, 256>>>(p_x1o, fc1_w, fc1_b, fc2_w, fc2_b, (float*)d_out);
}

// round 10
// speedup vs baseline: 1.2891x; 1.1069x over previous
#include <cuda_runtime.h>
#include <math.h>

#define BSZ 4

// ---------------- scratch (device globals; no allocations allowed) ----------
__device__ float g_v  [16777216];   // [4,64,256,256]
__device__ float g_x1d[ 4194304];   // [4,64,128,128]
__device__ float g_x2d[ 1572864];   // [4,96,64,64]
__device__ float g_xb [ 2097152];   // [4,128,64,64]
__device__ float g_x2c[14680064];   // [4,224,128,128] (x2 at coff 128)
__device__ float g_x2o[ 6291456];   // [4,96,128,128]
__device__ float g_x1c[41943040];   // [4,160,256,256] (x1 at coff 96)
__device__ float g_x1o[16777216];   // [4,64,256,256]

__device__ float g_XW [ 3932160];   // transposed: [H][BC*m2c]
__device__ float g_XF [  368640];   // [BC,2m1,m2] complex
__device__ float g_OF [  368640];   // [B,Co,2m1,m2] complex
__device__ float g_Z  [ 1572864];   // [B,Co,H,m2] complex (scaled)
__device__ float g_tw [   26112];   // twiddle tables (complex interleaved)

#define TW0 0
#define TH0 3072
#define TW1 9216
#define TH1 10240
#define TW2 12288
#define TH2 12544

__device__ __forceinline__ float gelu_f(float x) {
    return 0.5f * x * (1.0f + erff(x * 0.70710678118654752f));
}

// ---------------- twiddle init -----------------------------------------------
__global__ void k_init_tw() {
    const int cfg[3][5] = {{256,12,12,TW0,TH0},{128,8,8,TW1,TH1},{64,4,4,TW2,TH2}};
    int tid = blockIdx.x * blockDim.x + threadIdx.x;
    int nth = gridDim.x * blockDim.x;
    for (int c = 0; c < 3; c++) {
        int H = cfg[c][0], m1 = cfg[c][1], m2 = cfg[c][2];
        int offW = cfg[c][3], offH = cfg[c][4];
        int nW = H * m2;
        for (int e = tid; e < nW; e += nth) {
            int w = e / m2, kw = e % m2;
            int p = (w * kw) % H;
            double s, co; sincos(2.0 * 3.14159265358979323846 * (double)p / (double)H, &s, &co);
            g_tw[(offW + e) * 2]     = (float)co;
            g_tw[(offW + e) * 2 + 1] = (float)(-s);
        }
        int m1t2 = 2 * m1;
        int nH = H * m1t2;
        for (int e = tid; e < nH; e += nth) {
            int h = e / m1t2, j = e % m1t2;
            int kh = (j < m1) ? j : (H - 2 * m1 + j);
            int p = (kh * h) % H;
            double s, co; sincos(2.0 * 3.14159265358979323846 * (double)p / (double)H, &s, &co);
            g_tw[(offH + e) * 2]     = (float)co;
            g_tw[(offH + e) * 2 + 1] = (float)(-s);
        }
    }
}

// ---------------- lift: tiled 64px x 64c (proven in R7 run) ------------------
__global__ void k_lift(const float* __restrict__ x, const float* __restrict__ w,
                       const float* __restrict__ bb) {
    __shared__ float xs6[64][8];
    __shared__ float ws6[64][8];
    const int HW = 256 * 256;
    int b  = blockIdx.x >> 10;
    int p0 = (blockIdx.x & 1023) << 6;
    int tid = threadIdx.x;

    const float* xp = x + ((size_t)b * HW + p0) * 6;
    for (int l = tid; l < 384; l += 256) xs6[l / 6][l % 6] = xp[l];
    for (int l = tid; l < 384; l += 256) ws6[l / 6][l % 6] = w[l];
    __syncthreads();

    int ty = tid >> 4, tx = tid & 15;
    #pragma unroll
    for (int cr = 0; cr < 4; cr++) {
        int c = ty * 4 + cr;
        float bias = bb[c];
        float res[4];
        #pragma unroll
        for (int pc = 0; pc < 4; pc++) {
            int p = tx * 4 + pc;
            float acc = bias;
            #pragma unroll
            for (int k = 0; k < 6; k++) acc += ws6[c][k] * xs6[p][k];
            res[pc] = acc;
        }
        *(float4*)(g_v + (size_t)(b * 64 + c) * HW + p0 + tx * 4) =
            make_float4(res[0], res[1], res[2], res[3]);
    }
}

// ------- fwd DFT along W: register-prefetch double buffering -----------------
__global__ void k_fwd_w(const float* __restrict__ xin, int H, int W, int m2,
                        const float* __restrict__ tw, int BC) {
    __shared__ float xs[64][68];
    __shared__ float tws[64][24];
    int m2c = 2 * m2;
    int r0 = blockIdx.x * 64;
    int tid = threadIdx.x;
    int row_l = tid & 31;
    int kc0 = tid >> 5;
    bool v1 = (kc0 + 8 < m2c), v2 = (kc0 + 16 < m2c);
    float a00 = 0.f, a01 = 0.f, a02 = 0.f, a10 = 0.f, a11 = 0.f, a12 = 0.f;

    int pr = tid >> 4, pk4 = (tid & 15) * 4;   // this thread's 4 staging rows
    float4 xp0, xp1, xp2, xp3;
    {
        const float* bptr = xin + (size_t)(r0 + pr) * W + pk4;
        xp0 = *(const float4*)(bptr);
        xp1 = *(const float4*)(bptr + (size_t)16 * W);
        xp2 = *(const float4*)(bptr + (size_t)32 * W);
        xp3 = *(const float4*)(bptr + (size_t)48 * W);
    }

    int nchunks = W >> 6;
    for (int cidx = 0; cidx < nchunks; cidx++) {
        int k0 = cidx << 6;
        __syncthreads();
        *(float4*)&xs[pr][pk4]      = xp0;
        *(float4*)&xs[pr + 16][pk4] = xp1;
        *(float4*)&xs[pr + 32][pk4] = xp2;
        *(float4*)&xs[pr + 48][pk4] = xp3;
        for (int l = tid; l < 64 * m2c; l += 256) {
            int k = l / m2c, kc = l % m2c;
            tws[k][kc] = tw[(size_t)(k0 + k) * m2c + kc];
        }
        __syncthreads();
        if (cidx + 1 < nchunks) {
            const float* bptr = xin + (size_t)(r0 + pr) * W + k0 + 64 + pk4;
            xp0 = *(const float4*)(bptr);
            xp1 = *(const float4*)(bptr + (size_t)16 * W);
            xp2 = *(const float4*)(bptr + (size_t)32 * W);
            xp3 = *(const float4*)(bptr + (size_t)48 * W);
        }
        #pragma unroll 4
        for (int k = 0; k < 64; k++) {
            float x0 = xs[row_l][k];
            float x1 = xs[row_l + 32][k];
            float t0 = tws[k][kc0];
            a00 += x0 * t0; a10 += x1 * t0;
            if (v1) { float t1 = tws[k][kc0 + 8];  a01 += x0 * t1; a11 += x1 * t1; }
            if (v2) { float t2 = tws[k][kc0 + 16]; a02 += x0 * t2; a12 += x1 * t2; }
        }
    }
    int r = r0 + row_l;
    int bc = r / H, h = r - bc * H;
    size_t base = ((size_t)h * BC + bc) * m2c;
    g_XW[base + kc0] = a00;
    if (v1) g_XW[base + kc0 + 8]  = a01;
    if (v2) g_XW[base + kc0 + 16] = a02;
    r = r0 + row_l + 32;
    bc = r / H; h = r - bc * H;
    base = ((size_t)h * BC + bc) * m2c;
    g_XW[base + kc0] = a10;
    if (v1) g_XW[base + kc0 + 8]  = a11;
    if (v2) g_XW[base + kc0 + 16] = a12;
}

// ------- fwd DFT along H: 256 threads, 16 complex cols per block -------------
__global__ void k_fwd_h(int H, int BCm2, int m1, int m2, const float* __restrict__ tw) {
    __shared__ float xs[64][32];
    __shared__ float tws[64][48];
    int m1t2 = 2 * m1;
    int cc0 = blockIdx.x * 16;
    int tid = threadIdx.x;
    int cl = tid & 15;
    int g  = tid >> 4;          // 0..15
    bool v0 = (g < m1t2);
    bool v1 = (g + 16 < m1t2);
    float ar0 = 0.f, ai0 = 0.f, ar1 = 0.f, ai1 = 0.f;
    int N2 = BCm2 * 2;

    for (int h0 = 0; h0 < H; h0 += 64) {
        for (int l = tid; l < 64 * 8; l += 256) {
            int hh = l >> 3, c4 = (l & 7) * 4;
            *(float4*)&xs[hh][c4] =
                *(const float4*)(g_XW + (size_t)(h0 + hh) * N2 + cc0 * 2 + c4);
        }
        for (int l = tid; l < 64 * m1t2 * 2; l += 256) {
            int hh = l / (m1t2 * 2), c = l % (m1t2 * 2);
            tws[hh][c] = tw[(size_t)(h0 + hh) * m1t2 * 2 + c];
        }
        __syncthreads();
        #pragma unroll 4
        for (int hh = 0; hh < 64; hh++) {
            float2 xv = *(const float2*)&xs[hh][2 * cl];
            if (v0) {
                float tr = tws[hh][2 * g], ti = tws[hh][2 * g + 1];
                ar0 += xv.x * tr - xv.y * ti;
                ai0 += xv.x * ti + xv.y * tr;
            }
            if (v1) {
                float tr1 = tws[hh][2 * (g + 16)], ti1 = tws[hh][2 * (g + 16) + 1];
                ar1 += xv.x * tr1 - xv.y * ti1;
                ai1 += xv.x * ti1 + xv.y * tr1;
            }
        }
        __syncthreads();
    }
    int cc = cc0 + cl, bc = cc / m2, kw = cc % m2;
    if (v0) {
        size_t oo = (((size_t)bc * m1t2 + g) * m2 + kw) * 2;
        g_XF[oo] = ar0; g_XF[oo + 1] = ai0;
    }
    if (v1) {
        size_t oo = (((size_t)bc * m1t2 + g + 16) * m2 + kw) * 2;
        g_XF[oo] = ar1; g_XF[oo + 1] = ai1;
    }
}

// ------- per-mode channel mix; Co split over blockIdx.y -----------------------
__global__ void k_mix(int Ci, int Co, int m1, int m2,
                      const float* __restrict__ w1, const float* __restrict__ w2) {
    __shared__ float xf_s[3840];
    int m1t2 = 2 * m1, m2c = 2 * m2;
    int kk = blockIdx.x % m1t2;
    int b  = blockIdx.x / m1t2;
    int oy = blockIdx.y;
    int tid = threadIdx.x;

    for (int l = tid; l < Ci * m2c; l += 256) {
        int i = l / m2c, kc = l % m2c;
        xf_s[l] = g_XF[(((size_t)(b * Ci + i) * m1t2 + kk) * m2) * 2 + kc];
    }
    __syncthreads();

    int kkr = (kk < m1) ? kk : kk - m1;
    const float* wsel = (kk < m1) ? w1 : w2;
    int wstride = Co * m1 * m2 * 2;
    int nout = Co * m2;
    int half = nout >> 1;
    int e_begin = oy * half;
    int e_end   = e_begin + half;
    for (int e0 = e_begin + tid; e0 < e_end; e0 += 1024) {
        float orr[4] = {0,0,0,0}, oii[4] = {0,0,0,0};
        int xoff[4], woff[4]; bool val[4];
        #pragma unroll
        for (int u = 0; u < 4; u++) {
            int e = e0 + 256 * u;
            val[u] = (e < e_end);
            int kw = val[u] ? e % m2 : 0;
            int o  = val[u] ? e / m2 : 0;
            xoff[u] = 2 * kw;
            woff[u] = ((o * m1 + kkr) * m2 + kw) * 2;
        }
        for (int i = 0; i < Ci; i++) {
            const float* wrow = wsel + (size_t)i * wstride;
            const float* xrow = xf_s + i * m2c;
            #pragma unroll
            for (int u = 0; u < 4; u++) {
                float xr = xrow[xoff[u]], xi = xrow[xoff[u] + 1];
                float wr = wrow[woff[u]], wi = wrow[woff[u] + 1];
                orr[u] += xr * wr - xi * wi;
                oii[u] += xr * wi + xi * wr;
            }
        }
        #pragma unroll
        for (int u = 0; u < 4; u++) {
            if (val[u]) {
                int e = e0 + 256 * u;
                int kw = e % m2, o = e / m2;
                size_t oo = (((size_t)(b * Co + o) * m1t2 + kk) * m2 + kw) * 2;
                g_OF[oo] = orr[u]; g_OF[oo + 1] = oii[u];
            }
        }
    }
}

// ------- inverse DFT along H ---------------------------------------------------
__global__ void k_inv_h(int H, int m1, int m2, const float* __restrict__ tw,
                        float invHW) {
    __shared__ float of_s[1152];
    int bo = blockIdx.x;
    int tid = threadIdx.x;
    int m1t2 = 2 * m1;
    int nload = m1t2 * m2 * 2;
    const float* src = g_OF + (size_t)bo * nload;
    for (int l = tid; l < nload; l += 256) of_s[l] = src[l];
    __syncthreads();

    int nout = H * m2;
    for (int e = tid; e < nout; e += 512) {
        int e2 = e + 256;
        bool v2 = (e2 < nout);
        int kw0 = e % m2, h0 = e / m2;
        int kw1 = v2 ? e2 % m2 : 0, h1 = v2 ? e2 / m2 : 0;
        float zr0 = 0.f, zi0 = 0.f, zr1 = 0.f, zi1 = 0.f;
        for (int kk = 0; kk < m1t2; kk++) {
            float tr0 = tw[(h0 * m1t2 + kk) * 2], ti0 = tw[(h0 * m1t2 + kk) * 2 + 1];
            float fr0 = of_s[(kk * m2 + kw0) * 2], fi0 = of_s[(kk * m2 + kw0) * 2 + 1];
            zr0 += fr0 * tr0 + fi0 * ti0;
            zi0 += fi0 * tr0 - fr0 * ti0;
            float tr1 = tw[(h1 * m1t2 + kk) * 2], ti1 = tw[(h1 * m1t2 + kk) * 2 + 1];
            float fr1 = of_s[(kk * m2 + kw1) * 2], fi1 = of_s[(kk * m2 + kw1) * 2 + 1];
            zr1 += fr1 * tr1 + fi1 * ti1;
            zi1 += fi1 * tr1 - fr1 * ti1;
        }
        size_t oo = ((size_t)bo * nout + e) * 2;
        g_Z[oo] = zr0 * invHW; g_Z[oo + 1] = zi0 * invHW;
        if (v2) {
            oo = ((size_t)bo * nout + e2) * 2;
            g_Z[oo] = zr1 * invHW; g_Z[oo + 1] = zi1 * invHW;
        }
    }
}

// ------- fused GEMM: out = gelu(conv1x1 + bias + invW(Z)) --------------------
__global__ void k_fuse(const float* __restrict__ xin, int Ci, int Co,
                       int H, int W, int m2, const float* __restrict__ tw,
                       const float* __restrict__ cw, const float* __restrict__ cb,
                       float* __restrict__ out, int Ct, int coff) {
    __shared__ float xs[32][68];
    __shared__ float wst[32][68];   // [i][o]
    __shared__ float zst[24][68];   // [r][o]
    __shared__ float twst[24][68];  // [r][p]

    const int HW = H * W;
    int tilesPerImg = HW >> 6;
    int b  = blockIdx.x / tilesPerImg;
    int p0 = (blockIdx.x % tilesPerImg) << 6;
    int ob = blockIdx.y << 6;
    int h  = p0 / W, w0 = p0 % W;
    int tid = threadIdx.x;
    int ty = tid >> 4, tx = tid & 15;
    int m2c = 2 * m2;

    for (int l = tid; l < m2c * 64; l += 256) {
        int r = l >> 6, o = l & 63;
        int oo = ob + o;
        float v = (oo < Co) ? g_Z[(((size_t)(b * Co + oo) * H + h) * m2) * 2 + r] : 0.f;
        zst[r][o] = (r >= 2) ? 2.0f * v : v;
    }
    for (int l = tid; l < m2c * 64; l += 256) {
        int r = l >> 6, p = l & 63;
        twst[r][p] = tw[(size_t)(w0 + p) * m2c + r];
    }

    float4 xpre0, xpre1, wpre0, wpre1;
    {
        int l0 = tid, l1 = tid + 256;
        int i0 = l0 >> 4, q0 = (l0 & 15) * 4;
        int i1 = l1 >> 4, q1 = (l1 & 15) * 4;
        xpre0 = *(const float4*)(xin + (size_t)(b * Ci + i0) * HW + p0 + q0);
        xpre1 = *(const float4*)(xin + (size_t)(b * Ci + i1) * HW + p0 + q1);
        int o0 = l0 >> 3, j0 = (l0 & 7) * 4;
        int o1 = l1 >> 3, j1 = (l1 & 7) * 4;
        int oo0 = ob + o0, oo1 = ob + o1;
        wpre0 = (oo0 < Co) ? *(const float4*)(cw + (size_t)oo0 * Ci + j0)
                           : make_float4(0.f, 0.f, 0.f, 0.f);
        wpre1 = (oo1 < Co) ? *(const float4*)(cw + (size_t)oo1 * Ci + j1)
                           : make_float4(0.f, 0.f, 0.f, 0.f);
    }
    __syncthreads();

    float acc[4][4];
    #pragma unroll
    for (int r = 0; r < 4; r++)
        #pragma unroll
        for (int c = 0; c < 4; c++) acc[r][c] = 0.f;
    for (int r = 0; r < m2c; r++) {
        float4 zv = *(const float4*)&zst[r][ty * 4];
        float4 tv = *(const float4*)&twst[r][tx * 4];
        acc[0][0] += zv.x * tv.x; acc[0][1] += zv.x * tv.y;
        acc[0][2] += zv.x * tv.z; acc[0][3] += zv.x * tv.w;
        acc[1][0] += zv.y * tv.x; acc[1][1] += zv.y * tv.y;
        acc[1][2] += zv.y * tv.z; acc[1][3] += zv.y * tv.w;
        acc[2][0] += zv.z * tv.x; acc[2][1] += zv.z * tv.y;
        acc[2][2] += zv.z * tv.z; acc[2][3] += zv.z * tv.w;
        acc[3][0] += zv.w * tv.x; acc[3][1] += zv.w * tv.y;
        acc[3][2] += zv.w * tv.z; acc[3][3] += zv.w * tv.w;
    }

    for (int ci0 = 0; ci0 < Ci; ci0 += 32) {
        __syncthreads();
        {
            int l0 = tid, l1 = tid + 256;
            int i0 = l0 >> 4, q0 = (l0 & 15) * 4;
            int i1 = l1 >> 4, q1 = (l1 & 15) * 4;
            *(float4*)&xs[i0][q0] = xpre0;
            *(float4*)&xs[i1][q1] = xpre1;
            int o0 = l0 >> 3, j0 = (l0 & 7) * 4;
            int o1 = l1 >> 3, j1 = (l1 & 7) * 4;
            wst[j0][o0] = wpre0.x; wst[j0 + 1][o0] = wpre0.y;
            wst[j0 + 2][o0] = wpre0.z; wst[j0 + 3][o0] = wpre0.w;
            wst[j1][o1] = wpre1.x; wst[j1 + 1][o1] = wpre1.y;
            wst[j1 + 2][o1] = wpre1.z; wst[j1 + 3][o1] = wpre1.w;
        }
        __syncthreads();
        int cin = ci0 + 32;
        if (cin < Ci) {
            int l0 = tid, l1 = tid + 256;
            int i0 = l0 >> 4, q0 = (l0 & 15) * 4;
            int i1 = l1 >> 4, q1 = (l1 & 15) * 4;
            xpre0 = *(const float4*)(xin + (size_t)(b * Ci + cin + i0) * HW + p0 + q0);
            xpre1 = *(const float4*)(xin + (size_t)(b * Ci + cin + i1) * HW + p0 + q1);
            int o0 = l0 >> 3, j0 = (l0 & 7) * 4;
            int o1 = l1 >> 3, j1 = (l1 & 7) * 4;
            int oo0 = ob + o0, oo1 = ob + o1;
            wpre0 = (oo0 < Co) ? *(const float4*)(cw + (size_t)oo0 * Ci + cin + j0)
                               : make_float4(0.f, 0.f, 0.f, 0.f);
            wpre1 = (oo1 < Co) ? *(const float4*)(cw + (size_t)oo1 * Ci + cin + j1)
                               : make_float4(0.f, 0.f, 0.f, 0.f);
        }
        #pragma unroll
        for (int i = 0; i < 32; i++) {
            float4 xv = *(const float4*)&xs[i][tx * 4];
            float4 wv = *(const float4*)&wst[i][ty * 4];
            acc[0][0] += wv.x * xv.x; acc[0][1] += wv.x * xv.y;
            acc[0][2] += wv.x * xv.z; acc[0][3] += wv.x * xv.w;
            acc[1][0] += wv.y * xv.x; acc[1][1] += wv.y * xv.y;
            acc[1][2] += wv.y * xv.z; acc[1][3] += wv.y * xv.w;
            acc[2][0] += wv.z * xv.x; acc[2][1] += wv.z * xv.y;
            acc[2][2] += wv.z * xv.z; acc[2][3] += wv.z * xv.w;
            acc[3][0] += wv.w * xv.x; acc[3][1] += wv.w * xv.y;
            acc[3][2] += wv.w * xv.z; acc[3][3] += wv.w * xv.w;
        }
    }

    #pragma unroll
    for (int r = 0; r < 4; r++) {
        int oo = ob + ty * 4 + r;
        if (oo >= Co) continue;
        float bias = cb[oo];
        float res[4];
        #pragma unroll
        for (int c = 0; c < 4; c++) res[c] = gelu_f(acc[r][c] + bias);
        *(float4*)(out + (size_t)(b * Ct + coff + oo) * HW + p0 + tx * 4) =
            make_float4(res[0], res[1], res[2], res[3]);
    }
}

// ---------------- 2x2 mean pool (strided channel source) ---------------------
__global__ void k_pool(const float* __restrict__ in, int total, int C, int Ct, int coff,
                       int H, int W, float* __restrict__ out) {
    int idx = blockIdx.x * blockDim.x + threadIdx.x;
    if (idx >= total) return;
    int Ho = H / 2, Wo = W / 2;
    int wo = idx % Wo;
    int ho = (idx / Wo) % Ho;
    int c  = (idx / (Wo * Ho)) % C;
    int b  = idx / (Wo * Ho * C);
    const float* p = in + ((size_t)(b * Ct + coff + c) * H + 2 * ho) * W + 2 * wo;
    out[idx] = 0.25f * (p[0] + p[1] + p[W] + p[W + 1]);
}

// ------- bilinear 2x upsample: one thread = one 2x2 output quad --------------
__global__ void k_up(const float* __restrict__ in, int total, int C, int H, int W,
                     float* __restrict__ dst, int Ct, int coff) {
    int idx = blockIdx.x * blockDim.x + threadIdx.x;
    if (idx >= total) return;
    int wq = idx % W;
    int hq = (idx / W) % H;
    int c  = (idx / (W * H)) % C;
    int b  = idx / (W * H * C);

    const float* base = in + (size_t)(b * C + c) * H * W;
    int hm = (hq > 0) ? hq - 1 : 0;
    int hp = (hq < H - 1) ? hq + 1 : H - 1;
    int wm = (wq > 0) ? wq - 1 : 0;
    int wp = (wq < W - 1) ? wq + 1 : W - 1;

    float v00 = base[(size_t)hm * W + wm], v01 = base[(size_t)hm * W + wq], v02 = base[(size_t)hm * W + wp];
    float v10 = base[(size_t)hq * W + wm], v11 = base[(size_t)hq * W + wq], v12 = base[(size_t)hq * W + wp];
    float v20 = base[(size_t)hp * W + wm], v21 = base[(size_t)hp * W + wq], v22 = base[(size_t)hp * W + wp];

    float he0 = 0.25f * v00 + 0.75f * v01, ho0 = 0.75f * v01 + 0.25f * v02;
    float he1 = 0.25f * v10 + 0.75f * v11, ho1 = 0.75f * v11 + 0.25f * v12;
    float he2 = 0.25f * v20 + 0.75f * v21, ho2 = 0.75f * v21 + 0.25f * v22;

    int Ho = 2 * H, Wo = 2 * W;
    float* dp = dst + ((size_t)(b * Ct + coff + c) * Ho + 2 * hq) * Wo + 2 * wq;
    *(float2*)dp        = make_float2(0.25f * he0 + 0.75f * he1, 0.25f * ho0 + 0.75f * ho1);
    *(float2*)(dp + Wo) = make_float2(0.75f * he1 + 0.25f * he2, 0.75f * ho1 + 0.25f * ho2);
}

// ------- head: fc1(64->256)+gelu+fc2(256->3); w1 register-prefetch -----------
__global__ void k_head(const float* __restrict__ xin, const float* __restrict__ w1,
                       const float* __restrict__ b1, const float* __restrict__ w2,
                       const float* __restrict__ b2, float* __restrict__ out) {
    __shared__ float xs[64][68];
    __shared__ float wst[64][68];   // [i][o]
    __shared__ float red[16][200];

    const int HW = 256 * 256;
    int b  = blockIdx.x >> 10;
    int p0 = (blockIdx.x & 1023) * 64;
    int tid = threadIdx.x;
    int ty = tid >> 4, tx = tid & 15;

    for (int l = tid; l < 64 * 16; l += 256) {
        int i = l >> 4, p4 = (l & 15) * 4;
        *(float4*)&xs[i][p4] =
            *(const float4*)(xin + (size_t)(b * 64 + i) * HW + p0 + p4);
    }

    float4 wpre[4];
    #pragma unroll
    for (int u = 0; u < 4; u++) {
        int l = tid + 256 * u;
        int o = l >> 4, j = (l & 15) * 4;
        wpre[u] = *(const float4*)(w1 + (size_t)o * 64 + j);
    }

    float o3[3][4];
    #pragma unroll
    for (int cc = 0; cc < 3; cc++)
        #pragma unroll
        for (int c = 0; c < 4; c++) o3[cc][c] = 0.f;

    for (int oc = 0; oc < 4; oc++) {
        __syncthreads();
        #pragma unroll
        for (int u = 0; u < 4; u++) {
            int l = tid + 256 * u;
            int o = l >> 4, j = (l & 15) * 4;
            wst[j][o] = wpre[u].x; wst[j + 1][o] = wpre[u].y;
            wst[j + 2][o] = wpre[u].z; wst[j + 3][o] = wpre[u].w;
        }
        __syncthreads();
        if (oc < 3) {
            #pragma unroll
            for (int u = 0; u < 4; u++) {
                int l = tid + 256 * u;
                int o = l >> 4, j = (l & 15) * 4;
                wpre[u] = *(const float4*)(w1 + (size_t)((oc + 1) * 64 + o) * 64 + j);
            }
        }

        float acc[4][4];
        #pragma unroll
        for (int r = 0; r < 4; r++) {
            float bb = b1[oc * 64 + ty * 4 + r];
            #pragma unroll
            for (int c = 0; c < 4; c++) acc[r][c] = bb;
        }
        #pragma unroll
        for (int i = 0; i < 64; i++) {
            float4 xv = *(const float4*)&xs[i][tx * 4];
            float4 wv = *(const float4*)&wst[i][ty * 4];
            acc[0][0] += wv.x * xv.x; acc[0][1] += wv.x * xv.y;
            acc[0][2] += wv.x * xv.z; acc[0][3] += wv.x * xv.w;
            acc[1][0] += wv.y * xv.x; acc[1][1] += wv.y * xv.y;
            acc[1][2] += wv.y * xv.z; acc[1][3] += wv.y * xv.w;
            acc[2][0] += wv.z * xv.x; acc[2][1] += wv.z * xv.y;
            acc[2][2] += wv.z * xv.z; acc[2][3] += wv.z * xv.w;
            acc[3][0] += wv.w * xv.x; acc[3][1] += wv.w * xv.y;
            acc[3][2] += wv.w * xv.z; acc[3][3] += wv.w * xv.w;
        }
        #pragma unroll
        for (int r = 0; r < 4; r++) {
            int o = oc * 64 + ty * 4 + r;
            float w20 = w2[o], w21 = w2[256 + o], w22 = w2[512 + o];
            #pragma unroll
            for (int c = 0; c < 4; c++) {
                float hh = gelu_f(acc[r][c]);
                o3[0][c] += hh * w20;
                o3[1][c] += hh * w21;
                o3[2][c] += hh * w22;
            }
        }
    }

    __syncthreads();
    #pragma unroll
    for (int c = 0; c < 4; c++) {
        int p = tx * 4 + c;
        red[ty][p * 3 + 0] = o3[0][c];
        red[ty][p * 3 + 1] = o3[1][c];
        red[ty][p * 3 + 2] = o3[2][c];
    }
    __syncthreads();
    if (tid < 192) {
        int p = tid / 3, cc = tid % 3;
        float s = b2[cc];
        #pragma unroll
        for (int t = 0; t < 16; t++) s += red[t][p * 3 + cc];
        out[((size_t)b * HW + p0 + p) * 3 + cc] = s;
    }
}

// =============================================================================
static inline int grid_of(int total) { return (total + 255) / 256; }

static void spectral_block(const float* xin, int Ci, int Co, int H, int m1,
                           const float* w1, const float* w2,
                           const float* cw, const float* cb,
                           const float* twW, const float* twH,
                           float* out, int Ct, int coff) {
    const int W = H, m2 = m1, m1t2 = 2 * m1;
    int BC = BSZ * Ci;
    k_fwd_w<<<BC * H / 64, 256>>>(xin, H, W, m2, twW, BC);
    k_fwd_h<<<BC * m2 / 16, 256>>>(H, BC * m2, m1, m2, twH);
    dim3 mg(BSZ * m1t2, 2);
    k_mix<<<mg, 256>>>(Ci, Co, m1, m2, w1, w2);
    k_inv_h<<<BSZ * Co, 256>>>(H, m1, m2, twH, 1.0f / (float)(H * W));
    dim3 fg(BSZ * H * W / 64, (Co + 63) / 64);
    k_fuse<<<fg, 256>>>(xin, Ci, Co, H, W, m2, twW, cw, cb, out, Ct, coff);
}

extern "C" void kernel_launch(void* const* d_in, const int* in_sizes, int n_in,
                              void* d_out, int out_size) {
    const float* x      = (const float*)d_in[0];
    const float* fcin_w = (const float*)d_in[1];
    const float* fcin_b = (const float*)d_in[2];
    const float* sc1_w1 = (const float*)d_in[3];
    const float* sc1_w2 = (const float*)d_in[4];
    const float* c1_w   = (const float*)d_in[5];
    const float* c1_b   = (const float*)d_in[6];
    const float* sc2_w1 = (const float*)d_in[7];
    const float* sc2_w2 = (const float*)d_in[8];
    const float* c2_w   = (const float*)d_in[9];
    const float* c2_b   = (const float*)d_in[10];
    const float* scb_w1 = (const float*)d_in[11];
    const float* scb_w2 = (const float*)d_in[12];
    const float* cb_w   = (const float*)d_in[13];
    const float* cb_b   = (const float*)d_in[14];
    const float* su2_w1 = (const float*)d_in[15];
    const float* su2_w2 = (const float*)d_in[16];
    const float* u2_w   = (const float*)d_in[17];
    const float* u2_b   = (const float*)d_in[18];
    const float* su1_w1 = (const float*)d_in[19];
    const float* su1_w2 = (const float*)d_in[20];
    const float* u1_w   = (const float*)d_in[21];
    const float* u1_b   = (const float*)d_in[22];
    const float* fc1_w  = (const float*)d_in[23];
    const float* fc1_b  = (const float*)d_in[24];
    const float* fc2_w  = (const float*)d_in[25];
    const float* fc2_b  = (const float*)d_in[26];

    float *p_v, *p_x1d, *p_x2d, *p_xb, *p_x2c, *p_x2o, *p_x1c, *p_x1o, *p_tw;
    cudaGetSymbolAddress((void**)&p_v,   g_v);
    cudaGetSymbolAddress((void**)&p_x1d, g_x1d);
    cudaGetSymbolAddress((void**)&p_x2d, g_x2d);
    cudaGetSymbolAddress((void**)&p_xb,  g_xb);
    cudaGetSymbolAddress((void**)&p_x2c, g_x2c);
    cudaGetSymbolAddress((void**)&p_x2o, g_x2o);
    cudaGetSymbolAddress((void**)&p_x1c, g_x1c);
    cudaGetSymbolAddress((void**)&p_x1o, g_x1o);
    cudaGetSymbolAddress((void**)&p_tw,  g_tw);

    const float* tw_W0 = p_tw + 2 * TW0;
    const float* tw_H0 = p_tw + 2 * TH0;
    const float* tw_W1 = p_tw + 2 * TW1;
    const float* tw_H1 = p_tw + 2 * TH1;
    const float* tw_W2 = p_tw + 2 * TW2;
    const float* tw_H2 = p_tw + 2 * TH2;

    k_init_tw<<<32, 256>>>();

    // lift 6 -> 64 (tiled; x read once)
    k_lift<<<BSZ * 1024, 256>>>(x, fcin_w, fcin_b);

    // encoder level 1: 64 -> 64 @ 256 ; x1 written directly into x1c[96:160]
    spectral_block(p_v, 64, 64, 256, 12, sc1_w1, sc1_w2, c1_w, c1_b, tw_W0, tw_H0,
                   p_x1c, 160, 96);
    {
        int t = BSZ * 64 * 128 * 128;
        k_pool<<<grid_of(t), 256>>>(p_x1c, t, 64, 160, 96, 256, 256, p_x1d);
    }

    // encoder level 2: 64 -> 96 @ 128 ; x2 written into x2c[128:224]
    spectral_block(p_x1d, 64, 96, 128, 8, sc2_w1, sc2_w2, c2_w, c2_b, tw_W1, tw_H1,
                   p_x2c, 224, 128);
    {
        int t = BSZ * 96 * 64 * 64;
        k_pool<<<grid_of(t), 256>>>(p_x2c, t, 96, 224, 128, 128, 128, p_x2d);
    }

    // bottleneck: 96 -> 128 @ 64
    spectral_block(p_x2d, 96, 128, 64, 4, scb_w1, scb_w2, cb_w, cb_b, tw_W2, tw_H2,
                   p_xb, 128, 0);

    // up(xb) -> x2c[0:128]  (quad form: total = input elements)
    {
        int t = BSZ * 128 * 64 * 64;
        k_up<<<grid_of(t), 256>>>(p_xb, t, 128, 64, 64, p_x2c, 224, 0);
    }

    // decoder level 2: 224 -> 96 @ 128
    spectral_block(p_x2c, 224, 96, 128, 8, su2_w1, su2_w2, u2_w, u2_b, tw_W1, tw_H1,
                   p_x2o, 96, 0);

    // up(x2o) -> x1c[0:96]
    {
        int t = BSZ * 96 * 128 * 128;
        k_up<<<grid_of(t), 256>>>(p_x2o, t, 96, 128, 128, p_x1c, 160, 0);
    }

    // decoder level 1: 160 -> 64 @ 256
    spectral_block(p_x1c, 160, 64, 256, 12, su1_w1, su1_w2, u1_w, u1_b, tw_W0, tw_H0,
                   p_x1o, 64, 0);

    // head: fc1 + gelu + fc2 fused
    k_head<<<BSZ * 1024, 256>>>(p_x1o, fc1_w, fc1_b, fc2_w, fc2_b, (float*)d_out);
}

// round 11
// speedup vs baseline: 1.3083x; 1.0150x over previous
#include <cuda_runtime.h>
#include <math.h>

#define BSZ 4

// ---------------- scratch (device globals; no allocations allowed) ----------
__device__ float g_v  [16777216];   // [4,64,256,256]
__device__ float g_x1d[ 4194304];   // [4,64,128,128]
__device__ float g_x2d[ 1572864];   // [4,96,64,64]
__device__ float g_xb [ 2097152];   // [4,128,64,64]
__device__ float g_x2c[14680064];   // [4,224,128,128] (x2 at coff 128)
__device__ float g_x2o[ 6291456];   // [4,96,128,128]
__device__ float g_x1c[41943040];   // [4,160,256,256] (x1 at coff 96)
__device__ float g_x1o[16777216];   // [4,64,256,256]

__device__ float g_XW [ 3932160];   // transposed: [H][BC*m2c]
__device__ float g_XF [  368640];   // [BC,2m1,m2] complex
__device__ float g_OF [  368640];   // [B,Co,2m1,m2] complex
__device__ float g_Z  [ 1572864];   // [B,Co,H,m2] complex (scaled)
__device__ float g_tw [   26112];   // twiddle tables (complex interleaved)

#define TW0 0
#define TH0 3072
#define TW1 9216
#define TH1 10240
#define TW2 12288
#define TH2 12544

__device__ __forceinline__ float gelu_f(float x) {
    return 0.5f * x * (1.0f + erff(x * 0.70710678118654752f));
}

// ---------------- twiddle init -----------------------------------------------
__global__ void k_init_tw() {
    const int cfg[3][5] = {{256,12,12,TW0,TH0},{128,8,8,TW1,TH1},{64,4,4,TW2,TH2}};
    int tid = blockIdx.x * blockDim.x + threadIdx.x;
    int nth = gridDim.x * blockDim.x;
    for (int c = 0; c < 3; c++) {
        int H = cfg[c][0], m1 = cfg[c][1], m2 = cfg[c][2];
        int offW = cfg[c][3], offH = cfg[c][4];
        int nW = H * m2;
        for (int e = tid; e < nW; e += nth) {
            int w = e / m2, kw = e % m2;
            int p = (w * kw) % H;
            double s, co; sincos(2.0 * 3.14159265358979323846 * (double)p / (double)H, &s, &co);
            g_tw[(offW + e) * 2]     = (float)co;
            g_tw[(offW + e) * 2 + 1] = (float)(-s);
        }
        int m1t2 = 2 * m1;
        int nH = H * m1t2;
        for (int e = tid; e < nH; e += nth) {
            int h = e / m1t2, j = e % m1t2;
            int kh = (j < m1) ? j : (H - 2 * m1 + j);
            int p = (kh * h) % H;
            double s, co; sincos(2.0 * 3.14159265358979323846 * (double)p / (double)H, &s, &co);
            g_tw[(offH + e) * 2]     = (float)co;
            g_tw[(offH + e) * 2 + 1] = (float)(-s);
        }
    }
}

// ---------------- lift: tiled 64px x 64c -------------------------------------
__global__ void k_lift(const float* __restrict__ x, const float* __restrict__ w,
                       const float* __restrict__ bb) {
    __shared__ float xs6[64][8];
    __shared__ float ws6[64][8];
    const int HW = 256 * 256;
    int b  = blockIdx.x >> 10;
    int p0 = (blockIdx.x & 1023) << 6;
    int tid = threadIdx.x;

    const float* xp = x + ((size_t)b * HW + p0) * 6;
    for (int l = tid; l < 384; l += 256) xs6[l / 6][l % 6] = xp[l];
    for (int l = tid; l < 384; l += 256) ws6[l / 6][l % 6] = w[l];
    __syncthreads();

    int ty = tid >> 4, tx = tid & 15;
    #pragma unroll
    for (int cr = 0; cr < 4; cr++) {
        int c = ty * 4 + cr;
        float bias = bb[c];
        float res[4];
        #pragma unroll
        for (int pc = 0; pc < 4; pc++) {
            int p = tx * 4 + pc;
            float acc = bias;
            #pragma unroll
            for (int k = 0; k < 6; k++) acc += ws6[c][k] * xs6[p][k];
            res[pc] = acc;
        }
        *(float4*)(g_v + (size_t)(b * 64 + c) * HW + p0 + tx * 4) =
            make_float4(res[0], res[1], res[2], res[3]);
    }
}

// ------- fwd DFT along W with real-input symmetry (half the MACs) ------------
// 32 rows/block; in-place fold: raw[w]=x[w]+x[W-w], raw[W-w]=x[w]-x[W-w].
// Even kc (cos) reads raw[w]; odd kc (-sin) reads raw[W-w]. Thread kc parity fixed.
__global__ void k_fwd_w(const float* __restrict__ xin, int H, int W, int m2,
                        const float* __restrict__ tw, int BC) {
    __shared__ float raw[32][260];       // row stride 1040B (16B-aligned)
    __shared__ float tws[129][25];
    int m2c = 2 * m2;
    int Wh = W >> 1;
    int r0 = blockIdx.x * 32;
    int tid = threadIdx.x;
    int row_l = tid >> 3;                // 0..31
    int kc0 = tid & 7;                   // parity fixed; +8/+16 preserve parity
    bool odd = (kc0 & 1);
    bool v1 = (kc0 + 8 < m2c), v2 = (kc0 + 16 < m2c);

    int nf4 = W >> 2;
    for (int l = tid; l < 32 * nf4; l += 256) {
        int r = l / nf4, q = (l % nf4) * 4;
        *(float4*)&raw[r][q] = *(const float4*)(xin + (size_t)(r0 + r) * W + q);
    }
    for (int l = tid; l < (Wh + 1) * m2c; l += 256) {
        int w = l / m2c, kc = l % m2c;
        tws[w][kc] = tw[(size_t)w * m2c + kc];
    }
    __syncthreads();

    // in-place s/d fold: one thread owns both elements of each pair
    for (int l = tid; l < 32 * (Wh - 1); l += 256) {
        int r = l / (Wh - 1), w = 1 + l % (Wh - 1);
        float a = raw[r][w], bv = raw[r][W - w];
        raw[r][w]     = a + bv;
        raw[r][W - w] = a - bv;
    }
    __syncthreads();

    float a0, a1 = 0.f, a2 = 0.f;
    {
        float x0 = raw[row_l][0], xh = raw[row_l][Wh];
        a0 = x0 * tws[0][kc0] + xh * tws[Wh][kc0];
        if (v1) a1 = x0 * tws[0][kc0 + 8]  + xh * tws[Wh][kc0 + 8];
        if (v2) a2 = x0 * tws[0][kc0 + 16] + xh * tws[Wh][kc0 + 16];
    }
    const float* rrow = raw[row_l];
    #pragma unroll 4
    for (int w = 1; w < Wh; w++) {
        float xv = rrow[odd ? (W - w) : w];
        a0 += xv * tws[w][kc0];
        if (v1) a1 += xv * tws[w][kc0 + 8];
        if (v2) a2 += xv * tws[w][kc0 + 16];
    }
    int r = r0 + row_l;
    int bc = r / H, h = r - bc * H;
    size_t base = ((size_t)h * BC + bc) * m2c;
    g_XW[base + kc0] = a0;
    if (v1) g_XW[base + kc0 + 8]  = a1;
    if (v2) g_XW[base + kc0 + 16] = a2;
}

// ------- fwd DFT along H: 256 threads, 16 complex cols per block -------------
__global__ void k_fwd_h(int H, int BCm2, int m1, int m2, const float* __restrict__ tw) {
    __shared__ float xs[64][32];
    __shared__ float tws[64][48];
    int m1t2 = 2 * m1;
    int cc0 = blockIdx.x * 16;
    int tid = threadIdx.x;
    int cl = tid & 15;
    int g  = tid >> 4;          // 0..15
    bool v0 = (g < m1t2);
    bool v1 = (g + 16 < m1t2);
    float ar0 = 0.f, ai0 = 0.f, ar1 = 0.f, ai1 = 0.f;
    int N2 = BCm2 * 2;

    for (int h0 = 0; h0 < H; h0 += 64) {
        for (int l = tid; l < 64 * 8; l += 256) {
            int hh = l >> 3, c4 = (l & 7) * 4;
            *(float4*)&xs[hh][c4] =
                *(const float4*)(g_XW + (size_t)(h0 + hh) * N2 + cc0 * 2 + c4);
        }
        for (int l = tid; l < 64 * m1t2 * 2; l += 256) {
            int hh = l / (m1t2 * 2), c = l % (m1t2 * 2);
            tws[hh][c] = tw[(size_t)(h0 + hh) * m1t2 * 2 + c];
        }
        __syncthreads();
        #pragma unroll 4
        for (int hh = 0; hh < 64; hh++) {
            float2 xv = *(const float2*)&xs[hh][2 * cl];
            if (v0) {
                float tr = tws[hh][2 * g], ti = tws[hh][2 * g + 1];
                ar0 += xv.x * tr - xv.y * ti;
                ai0 += xv.x * ti + xv.y * tr;
            }
            if (v1) {
                float tr1 = tws[hh][2 * (g + 16)], ti1 = tws[hh][2 * (g + 16) + 1];
                ar1 += xv.x * tr1 - xv.y * ti1;
                ai1 += xv.x * ti1 + xv.y * tr1;
            }
        }
        __syncthreads();
    }
    int cc = cc0 + cl, bc = cc / m2, kw = cc % m2;
    if (v0) {
        size_t oo = (((size_t)bc * m1t2 + g) * m2 + kw) * 2;
        g_XF[oo] = ar0; g_XF[oo + 1] = ai0;
    }
    if (v1) {
        size_t oo = (((size_t)bc * m1t2 + g + 16) * m2 + kw) * 2;
        g_XF[oo] = ar1; g_XF[oo + 1] = ai1;
    }
}

// ------- per-mode channel mix; Co split over blockIdx.y -----------------------
__global__ void k_mix(int Ci, int Co, int m1, int m2,
                      const float* __restrict__ w1, const float* __restrict__ w2) {
    __shared__ float xf_s[3840];
    int m1t2 = 2 * m1, m2c = 2 * m2;
    int kk = blockIdx.x % m1t2;
    int b  = blockIdx.x / m1t2;
    int oy = blockIdx.y;
    int tid = threadIdx.x;

    for (int l = tid; l < Ci * m2c; l += 256) {
        int i = l / m2c, kc = l % m2c;
        xf_s[l] = g_XF[(((size_t)(b * Ci + i) * m1t2 + kk) * m2) * 2 + kc];
    }
    __syncthreads();

    int kkr = (kk < m1) ? kk : kk - m1;
    const float* wsel = (kk < m1) ? w1 : w2;
    int wstride = Co * m1 * m2 * 2;
    int nout = Co * m2;
    int half = nout >> 1;
    int e_begin = oy * half;
    int e_end   = e_begin + half;
    for (int e0 = e_begin + tid; e0 < e_end; e0 += 1024) {
        float orr[4] = {0,0,0,0}, oii[4] = {0,0,0,0};
        int xoff[4], woff[4]; bool val[4];
        #pragma unroll
        for (int u = 0; u < 4; u++) {
            int e = e0 + 256 * u;
            val[u] = (e < e_end);
            int kw = val[u] ? e % m2 : 0;
            int o  = val[u] ? e / m2 : 0;
            xoff[u] = 2 * kw;
            woff[u] = ((o * m1 + kkr) * m2 + kw) * 2;
        }
        for (int i = 0; i < Ci; i++) {
            const float* wrow = wsel + (size_t)i * wstride;
            const float* xrow = xf_s + i * m2c;
            #pragma unroll
            for (int u = 0; u < 4; u++) {
                float xr = xrow[xoff[u]], xi = xrow[xoff[u] + 1];
                float wr = wrow[woff[u]], wi = wrow[woff[u] + 1];
                orr[u] += xr * wr - xi * wi;
                oii[u] += xr * wi + xi * wr;
            }
        }
        #pragma unroll
        for (int u = 0; u < 4; u++) {
            if (val[u]) {
                int e = e0 + 256 * u;
                int kw = e % m2, o = e / m2;
                size_t oo = (((size_t)(b * Co + o) * m1t2 + kk) * m2 + kw) * 2;
                g_OF[oo] = orr[u]; g_OF[oo + 1] = oii[u];
            }
        }
    }
}

// ------- inverse DFT along H; H rows split over blockIdx.y --------------------
__global__ void k_inv_h(int H, int m1, int m2, const float* __restrict__ tw,
                        float invHW) {
    __shared__ float of_s[1152];
    int bo = blockIdx.x;
    int hy = blockIdx.y;
    int tid = threadIdx.x;
    int m1t2 = 2 * m1;
    int nload = m1t2 * m2 * 2;
    const float* src = g_OF + (size_t)bo * nload;
    for (int l = tid; l < nload; l += 256) of_s[l] = src[l];
    __syncthreads();

    int nout = H * m2;
    int nh = nout >> 1;
    int e_begin = hy * nh;
    int e_end = e_begin + nh;
    for (int e = e_begin + tid; e < e_end; e += 512) {
        int e2 = e + 256;
        bool v2 = (e2 < e_end);
        int kw0 = e % m2, h0 = e / m2;
        int kw1 = v2 ? e2 % m2 : 0, h1 = v2 ? e2 / m2 : 0;
        float zr0 = 0.f, zi0 = 0.f, zr1 = 0.f, zi1 = 0.f;
        for (int kk = 0; kk < m1t2; kk++) {
            float tr0 = tw[(h0 * m1t2 + kk) * 2], ti0 = tw[(h0 * m1t2 + kk) * 2 + 1];
            float fr0 = of_s[(kk * m2 + kw0) * 2], fi0 = of_s[(kk * m2 + kw0) * 2 + 1];
            zr0 += fr0 * tr0 + fi0 * ti0;
            zi0 += fi0 * tr0 - fr0 * ti0;
            float tr1 = tw[(h1 * m1t2 + kk) * 2], ti1 = tw[(h1 * m1t2 + kk) * 2 + 1];
            float fr1 = of_s[(kk * m2 + kw1) * 2], fi1 = of_s[(kk * m2 + kw1) * 2 + 1];
            zr1 += fr1 * tr1 + fi1 * ti1;
            zi1 += fi1 * tr1 - fr1 * ti1;
        }
        size_t oo = ((size_t)bo * nout + e) * 2;
        g_Z[oo] = zr0 * invHW; g_Z[oo + 1] = zi0 * invHW;
        if (v2) {
            oo = ((size_t)bo * nout + e2) * 2;
            g_Z[oo] = zr1 * invHW; g_Z[oo + 1] = zi1 * invHW;
        }
    }
}

// ------- fused GEMM: out = gelu(conv1x1 + bias + invW(Z)) --------------------
__global__ void k_fuse(const float* __restrict__ xin, int Ci, int Co,
                       int H, int W, int m2, const float* __restrict__ tw,
                       const float* __restrict__ cw, const float* __restrict__ cb,
                       float* __restrict__ out, int Ct, int coff) {
    __shared__ float xs[32][68];
    __shared__ float wst[32][68];   // [i][o]
    __shared__ float zst[24][68];   // [r][o]
    __shared__ float twst[24][68];  // [r][p]

    const int HW = H * W;
    int tilesPerImg = HW >> 6;
    int b  = blockIdx.x / tilesPerImg;
    int p0 = (blockIdx.x % tilesPerImg) << 6;
    int ob = blockIdx.y << 6;
    int h  = p0 / W, w0 = p0 % W;
    int tid = threadIdx.x;
    int ty = tid >> 4, tx = tid & 15;
    int m2c = 2 * m2;

    for (int l = tid; l < m2c * 64; l += 256) {
        int r = l >> 6, o = l & 63;
        int oo = ob + o;
        float v = (oo < Co) ? g_Z[(((size_t)(b * Co + oo) * H + h) * m2) * 2 + r] : 0.f;
        zst[r][o] = (r >= 2) ? 2.0f * v : v;
    }
    for (int l = tid; l < m2c * 64; l += 256) {
        int r = l >> 6, p = l & 63;
        twst[r][p] = tw[(size_t)(w0 + p) * m2c + r];
    }

    float4 xpre0, xpre1, wpre0, wpre1;
    {
        int l0 = tid, l1 = tid + 256;
        int i0 = l0 >> 4, q0 = (l0 & 15) * 4;
        int i1 = l1 >> 4, q1 = (l1 & 15) * 4;
        xpre0 = *(const float4*)(xin + (size_t)(b * Ci + i0) * HW + p0 + q0);
        xpre1 = *(const float4*)(xin + (size_t)(b * Ci + i1) * HW + p0 + q1);
        int o0 = l0 >> 3, j0 = (l0 & 7) * 4;
        int o1 = l1 >> 3, j1 = (l1 & 7) * 4;
        int oo0 = ob + o0, oo1 = ob + o1;
        wpre0 = (oo0 < Co) ? *(const float4*)(cw + (size_t)oo0 * Ci + j0)
                           : make_float4(0.f, 0.f, 0.f, 0.f);
        wpre1 = (oo1 < Co) ? *(const float4*)(cw + (size_t)oo1 * Ci + j1)
                           : make_float4(0.f, 0.f, 0.f, 0.f);
    }
    __syncthreads();

    float acc[4][4];
    #pragma unroll
    for (int r = 0; r < 4; r++)
        #pragma unroll
        for (int c = 0; c < 4; c++) acc[r][c] = 0.f;
    for (int r = 0; r < m2c; r++) {
        float4 zv = *(const float4*)&zst[r][ty * 4];
        float4 tv = *(const float4*)&twst[r][tx * 4];
        acc[0][0] += zv.x * tv.x; acc[0][1] += zv.x * tv.y;
        acc[0][2] += zv.x * tv.z; acc[0][3] += zv.x * tv.w;
        acc[1][0] += zv.y * tv.x; acc[1][1] += zv.y * tv.y;
        acc[1][2] += zv.y * tv.z; acc[1][3] += zv.y * tv.w;
        acc[2][0] += zv.z * tv.x; acc[2][1] += zv.z * tv.y;
        acc[2][2] += zv.z * tv.z; acc[2][3] += zv.z * tv.w;
        acc[3][0] += zv.w * tv.x; acc[3][1] += zv.w * tv.y;
        acc[3][2] += zv.w * tv.z; acc[3][3] += zv.w * tv.w;
    }

    for (int ci0 = 0; ci0 < Ci; ci0 += 32) {
        __syncthreads();
        {
            int l0 = tid, l1 = tid + 256;
            int i0 = l0 >> 4, q0 = (l0 & 15) * 4;
            int i1 = l1 >> 4, q1 = (l1 & 15) * 4;
            *(float4*)&xs[i0][q0] = xpre0;
            *(float4*)&xs[i1][q1] = xpre1;
            int o0 = l0 >> 3, j0 = (l0 & 7) * 4;
            int o1 = l1 >> 3, j1 = (l1 & 7) * 4;
            wst[j0][o0] = wpre0.x; wst[j0 + 1][o0] = wpre0.y;
            wst[j0 + 2][o0] = wpre0.z; wst[j0 + 3][o0] = wpre0.w;
            wst[j1][o1] = wpre1.x; wst[j1 + 1][o1] = wpre1.y;
            wst[j1 + 2][o1] = wpre1.z; wst[j1 + 3][o1] = wpre1.w;
        }
        __syncthreads();
        int cin = ci0 + 32;
        if (cin < Ci) {
            int l0 = tid, l1 = tid + 256;
            int i0 = l0 >> 4, q0 = (l0 & 15) * 4;
            int i1 = l1 >> 4, q1 = (l1 & 15) * 4;
            xpre0 = *(const float4*)(xin + (size_t)(b * Ci + cin + i0) * HW + p0 + q0);
            xpre1 = *(const float4*)(xin + (size_t)(b * Ci + cin + i1) * HW + p0 + q1);
            int o0 = l0 >> 3, j0 = (l0 & 7) * 4;
            int o1 = l1 >> 3, j1 = (l1 & 7) * 4;
            int oo0 = ob + o0, oo1 = ob + o1;
            wpre0 = (oo0 < Co) ? *(const float4*)(cw + (size_t)oo0 * Ci + cin + j0)
                               : make_float4(0.f, 0.f, 0.f, 0.f);
            wpre1 = (oo1 < Co) ? *(const float4*)(cw + (size_t)oo1 * Ci + cin + j1)
                               : make_float4(0.f, 0.f, 0.f, 0.f);
        }
        #pragma unroll
        for (int i = 0; i < 32; i++) {
            float4 xv = *(const float4*)&xs[i][tx * 4];
            float4 wv = *(const float4*)&wst[i][ty * 4];
            acc[0][0] += wv.x * xv.x; acc[0][1] += wv.x * xv.y;
            acc[0][2] += wv.x * xv.z; acc[0][3] += wv.x * xv.w;
            acc[1][0] += wv.y * xv.x; acc[1][1] += wv.y * xv.y;
            acc[1][2] += wv.y * xv.z; acc[1][3] += wv.y * xv.w;
            acc[2][0] += wv.z * xv.x; acc[2][1] += wv.z * xv.y;
            acc[2][2] += wv.z * xv.z; acc[2][3] += wv.z * xv.w;
            acc[3][0] += wv.w * xv.x; acc[3][1] += wv.w * xv.y;
            acc[3][2] += wv.w * xv.z; acc[3][3] += wv.w * xv.w;
        }
    }

    #pragma unroll
    for (int r = 0; r < 4; r++) {
        int oo = ob + ty * 4 + r;
        if (oo >= Co) continue;
        float bias = cb[oo];
        float res[4];
        #pragma unroll
        for (int c = 0; c < 4; c++) res[c] = gelu_f(acc[r][c] + bias);
        *(float4*)(out + (size_t)(b * Ct + coff + oo) * HW + p0 + tx * 4) =
            make_float4(res[0], res[1], res[2], res[3]);
    }
}

// ---------------- 2x2 mean pool (strided channel source) ---------------------
__global__ void k_pool(const float* __restrict__ in, int total, int C, int Ct, int coff,
                       int H, int W, float* __restrict__ out) {
    int idx = blockIdx.x * blockDim.x + threadIdx.x;
    if (idx >= total) return;
    int Ho = H / 2, Wo = W / 2;
    int wo = idx % Wo;
    int ho = (idx / Wo) % Ho;
    int c  = (idx / (Wo * Ho)) % C;
    int b  = idx / (Wo * Ho * C);
    const float* p = in + ((size_t)(b * Ct + coff + c) * H + 2 * ho) * W + 2 * wo;
    out[idx] = 0.25f * (p[0] + p[1] + p[W] + p[W + 1]);
}

// ------- bilinear 2x upsample: one thread = one 2x2 output quad --------------
__global__ void k_up(const float* __restrict__ in, int total, int C, int H, int W,
                     float* __restrict__ dst, int Ct, int coff) {
    int idx = blockIdx.x * blockDim.x + threadIdx.x;
    if (idx >= total) return;
    int wq = idx % W;
    int hq = (idx / W) % H;
    int c  = (idx / (W * H)) % C;
    int b  = idx / (W * H * C);

    const float* base = in + (size_t)(b * C + c) * H * W;
    int hm = (hq > 0) ? hq - 1 : 0;
    int hp = (hq < H - 1) ? hq + 1 : H - 1;
    int wm = (wq > 0) ? wq - 1 : 0;
    int wp = (wq < W - 1) ? wq + 1 : W - 1;

    float v00 = base[(size_t)hm * W + wm], v01 = base[(size_t)hm * W + wq], v02 = base[(size_t)hm * W + wp];
    float v10 = base[(size_t)hq * W + wm], v11 = base[(size_t)hq * W + wq], v12 = base[(size_t)hq * W + wp];
    float v20 = base[(size_t)hp * W + wm], v21 = base[(size_t)hp * W + wq], v22 = base[(size_t)hp * W + wp];

    float he0 = 0.25f * v00 + 0.75f * v01, ho0 = 0.75f * v01 + 0.25f * v02;
    float he1 = 0.25f * v10 + 0.75f * v11, ho1 = 0.75f * v11 + 0.25f * v12;
    float he2 = 0.25f * v20 + 0.75f * v21, ho2 = 0.75f * v21 + 0.25f * v22;

    int Ho = 2 * H, Wo = 2 * W;
    float* dp = dst + ((size_t)(b * Ct + coff + c) * Ho + 2 * hq) * Wo + 2 * wq;
    *(float2*)dp        = make_float2(0.25f * he0 + 0.75f * he1, 0.25f * ho0 + 0.75f * ho1);
    *(float2*)(dp + Wo) = make_float2(0.75f * he1 + 0.25f * he2, 0.75f * ho1 + 0.25f * ho2);
}

// ------- head: fc1(64->256)+gelu+fc2(256->3); w1 register-prefetch -----------
__global__ void k_head(const float* __restrict__ xin, const float* __restrict__ w1,
                       const float* __restrict__ b1, const float* __restrict__ w2,
                       const float* __restrict__ b2, float* __restrict__ out) {
    __shared__ float xs[64][68];
    __shared__ float wst[64][68];   // [i][o]
    __shared__ float red[16][200];

    const int HW = 256 * 256;
    int b  = blockIdx.x >> 10;
    int p0 = (blockIdx.x & 1023) * 64;
    int tid = threadIdx.x;
    int ty = tid >> 4, tx = tid & 15;

    for (int l = tid; l < 64 * 16; l += 256) {
        int i = l >> 4, p4 = (l & 15) * 4;
        *(float4*)&xs[i][p4] =
            *(const float4*)(xin + (size_t)(b * 64 + i) * HW + p0 + p4);
    }

    float4 wpre[4];
    #pragma unroll
    for (int u = 0; u < 4; u++) {
        int l = tid + 256 * u;
        int o = l >> 4, j = (l & 15) * 4;
        wpre[u] = *(const float4*)(w1 + (size_t)o * 64 + j);
    }

    float o3[3][4];
    #pragma unroll
    for (int cc = 0; cc < 3; cc++)
        #pragma unroll
        for (int c = 0; c < 4; c++) o3[cc][c] = 0.f;

    for (int oc = 0; oc < 4; oc++) {
        __syncthreads();
        #pragma unroll
        for (int u = 0; u < 4; u++) {
            int l = tid + 256 * u;
            int o = l >> 4, j = (l & 15) * 4;
            wst[j][o] = wpre[u].x; wst[j + 1][o] = wpre[u].y;
            wst[j + 2][o] = wpre[u].z; wst[j + 3][o] = wpre[u].w;
        }
        __syncthreads();
        if (oc < 3) {
            #pragma unroll
            for (int u = 0; u < 4; u++) {
                int l = tid + 256 * u;
                int o = l >> 4, j = (l & 15) * 4;
                wpre[u] = *(const float4*)(w1 + (size_t)((oc + 1) * 64 + o) * 64 + j);
            }
        }

        float acc[4][4];
        #pragma unroll
        for (int r = 0; r < 4; r++) {
            float bb = b1[oc * 64 + ty * 4 + r];
            #pragma unroll
            for (int c = 0; c < 4; c++) acc[r][c] = bb;
        }
        #pragma unroll
        for (int i = 0; i < 64; i++) {
            float4 xv = *(const float4*)&xs[i][tx * 4];
            float4 wv = *(const float4*)&wst[i][ty * 4];
            acc[0][0] += wv.x * xv.x; acc[0][1] += wv.x * xv.y;
            acc[0][2] += wv.x * xv.z; acc[0][3] += wv.x * xv.w;
            acc[1][0] += wv.y * xv.x; acc[1][1] += wv.y * xv.y;
            acc[1][2] += wv.y * xv.z; acc[1][3] += wv.y * xv.w;
            acc[2][0] += wv.z * xv.x; acc[2][1] += wv.z * xv.y;
            acc[2][2] += wv.z * xv.z; acc[2][3] += wv.z * xv.w;
            acc[3][0] += wv.w * xv.x; acc[3][1] += wv.w * xv.y;
            acc[3][2] += wv.w * xv.z; acc[3][3] += wv.w * xv.w;
        }
        #pragma unroll
        for (int r = 0; r < 4; r++) {
            int o = oc * 64 + ty * 4 + r;
            float w20 = w2[o], w21 = w2[256 + o], w22 = w2[512 + o];
            #pragma unroll
            for (int c = 0; c < 4; c++) {
                float hh = gelu_f(acc[r][c]);
                o3[0][c] += hh * w20;
                o3[1][c] += hh * w21;
                o3[2][c] += hh * w22;
            }
        }
    }

    __syncthreads();
    #pragma unroll
    for (int c = 0; c < 4; c++) {
        int p = tx * 4 + c;
        red[ty][p * 3 + 0] = o3[0][c];
        red[ty][p * 3 + 1] = o3[1][c];
        red[ty][p * 3 + 2] = o3[2][c];
    }
    __syncthreads();
    if (tid < 192) {
        int p = tid / 3, cc = tid % 3;
        float s = b2[cc];
        #pragma unroll
        for (int t = 0; t < 16; t++) s += red[t][p * 3 + cc];
        out[((size_t)b * HW + p0 + p) * 3 + cc] = s;
    }
}

// =============================================================================
static inline int grid_of(int total) { return (total + 255) / 256; }

static void spectral_block(const float* xin, int Ci, int Co, int H, int m1,
                           const float* w1, const float* w2,
                           const float* cw, const float* cb,
                           const float* twW, const float* twH,
                           float* out, int Ct, int coff) {
    const int W = H, m2 = m1, m1t2 = 2 * m1;
    int BC = BSZ * Ci;
    k_fwd_w<<<BC * H / 32, 256>>>(xin, H, W, m2, twW, BC);
    k_fwd_h<<<BC * m2 / 16, 256>>>(H, BC * m2, m1, m2, twH);
    dim3 mg(BSZ * m1t2, 2);
    k_mix<<<mg, 256>>>(Ci, Co, m1, m2, w1, w2);
    dim3 ig(BSZ * Co, 2);
    k_inv_h<<<ig, 256>>>(H, m1, m2, twH, 1.0f / (float)(H * W));
    dim3 fg(BSZ * H * W / 64, (Co + 63) / 64);
    k_fuse<<<fg, 256>>>(xin, Ci, Co, H, W, m2, twW, cw, cb, out, Ct, coff);
}

extern "C" void kernel_launch(void* const* d_in, const int* in_sizes, int n_in,
                              void* d_out, int out_size) {
    const float* x      = (const float*)d_in[0];
    const float* fcin_w = (const float*)d_in[1];
    const float* fcin_b = (const float*)d_in[2];
    const float* sc1_w1 = (const float*)d_in[3];
    const float* sc1_w2 = (const float*)d_in[4];
    const float* c1_w   = (const float*)d_in[5];
    const float* c1_b   = (const float*)d_in[6];
    const float* sc2_w1 = (const float*)d_in[7];
    const float* sc2_w2 = (const float*)d_in[8];
    const float* c2_w   = (const float*)d_in[9];
    const float* c2_b   = (const float*)d_in[10];
    const float* scb_w1 = (const float*)d_in[11];
    const float* scb_w2 = (const float*)d_in[12];
    const float* cb_w   = (const float*)d_in[13];
    const float* cb_b   = (const float*)d_in[14];
    const float* su2_w1 = (const float*)d_in[15];
    const float* su2_w2 = (const float*)d_in[16];
    const float* u2_w   = (const float*)d_in[17];
    const float* u2_b   = (const float*)d_in[18];
    const float* su1_w1 = (const float*)d_in[19];
    const float* su1_w2 = (const float*)d_in[20];
    const float* u1_w   = (const float*)d_in[21];
    const float* u1_b   = (const float*)d_in[22];
    const float* fc1_w  = (const float*)d_in[23];
    const float* fc1_b  = (const float*)d_in[24];
    const float* fc2_w  = (const float*)d_in[25];
    const float* fc2_b  = (const float*)d_in[26];

    float *p_v, *p_x1d, *p_x2d, *p_xb, *p_x2c, *p_x2o, *p_x1c, *p_x1o, *p_tw;
    cudaGetSymbolAddress((void**)&p_v,   g_v);
    cudaGetSymbolAddress((void**)&p_x1d, g_x1d);
    cudaGetSymbolAddress((void**)&p_x2d, g_x2d);
    cudaGetSymbolAddress((void**)&p_xb,  g_xb);
    cudaGetSymbolAddress((void**)&p_x2c, g_x2c);
    cudaGetSymbolAddress((void**)&p_x2o, g_x2o);
    cudaGetSymbolAddress((void**)&p_x1c, g_x1c);
    cudaGetSymbolAddress((void**)&p_x1o, g_x1o);
    cudaGetSymbolAddress((void**)&p_tw,  g_tw);

    const float* tw_W0 = p_tw + 2 * TW0;
    const float* tw_H0 = p_tw + 2 * TH0;
    const float* tw_W1 = p_tw + 2 * TW1;
    const float* tw_H1 = p_tw + 2 * TH1;
    const float* tw_W2 = p_tw + 2 * TW2;
    const float* tw_H2 = p_tw + 2 * TH2;

    k_init_tw<<<32, 256>>>();

    // lift 6 -> 64 (tiled; x read once)
    k_lift<<<BSZ * 1024, 256>>>(x, fcin_w, fcin_b);

    // encoder level 1: 64 -> 64 @ 256 ; x1 written directly into x1c[96:160]
    spectral_block(p_v, 64, 64, 256, 12, sc1_w1, sc1_w2, c1_w, c1_b, tw_W0, tw_H0,
                   p_x1c, 160, 96);
    {
        int t = BSZ * 64 * 128 * 128;
        k_pool<<<grid_of(t), 256>>>(p_x1c, t, 64, 160, 96, 256, 256, p_x1d);
    }

    // encoder level 2: 64 -> 96 @ 128 ; x2 written into x2c[128:224]
    spectral_block(p_x1d, 64, 96, 128, 8, sc2_w1, sc2_w2, c2_w, c2_b, tw_W1, tw_H1,
                   p_x2c, 224, 128);
    {
        int t = BSZ * 96 * 64 * 64;
        k_pool<<<grid_of(t), 256>>>(p_x2c, t, 96, 224, 128, 128, 128, p_x2d);
    }

    // bottleneck: 96 -> 128 @ 64
    spectral_block(p_x2d, 96, 128, 64, 4, scb_w1, scb_w2, cb_w, cb_b, tw_W2, tw_H2,
                   p_xb, 128, 0);

    // up(xb) -> x2c[0:128]  (quad form: total = input elements)
    {
        int t = BSZ * 128 * 64 * 64;
        k_up<<<grid_of(t), 256>>>(p_xb, t, 128, 64, 64, p_x2c, 224, 0);
    }

    // decoder level 2: 224 -> 96 @ 128
    spectral_block(p_x2c, 224, 96, 128, 8, su2_w1, su2_w2, u2_w, u2_b, tw_W1, tw_H1,
                   p_x2o, 96, 0);

    // up(x2o) -> x1c[0:96]
    {
        int t = BSZ * 96 * 128 * 128;
        k_up<<<grid_of(t), 256>>>(p_x2o, t, 96, 128, 128, p_x1c, 160, 0);
    }

    // decoder level 1: 160 -> 64 @ 256
    spectral_block(p_x1c, 160, 64, 256, 12, su1_w1, su1_w2, u1_w, u1_b, tw_W0, tw_H0,
                   p_x1o, 64, 0);

    // head: fc1 + gelu + fc2 fused
    k_head<<<BSZ * 1024, 256>>>(p_x1o, fc1_w, fc1_b, fc2_w, fc2_b, (float*)d_out);
}